// round 13
// baseline (speedup 1.0000x reference)
#include <cuda_runtime.h>
#include <cuda_fp16.h>
#include <math.h>
#include <stdint.h>

// Problem constants
#define BB   2
#define LL   1024
#define DD   768
#define HH   12
#define HD   64
#define NLAY 2
#define DFFN 3072
#define VV   50257
#define EOS_ID 50256
#define ROWS (BB*LL)          // 2048

// ---------------------------------------------------------------------------
// Static scratch
// ---------------------------------------------------------------------------
__device__ float  g_x[ROWS*DD];
__device__ float  g_tmp[ROWS*DD];
__device__ int    g_rel[ROWS];
__device__ int    g_seg[ROWS];
// fp16 tensors
__device__ __half h_qkv[ROWS*3*DD];
__device__ __half h_x[ROWS*DD];
__device__ __half h_att[ROWS*DD];
__device__ __half h_ff[ROWS*DFFN];
__device__ __half h_tok[VV*DD];
__device__ __half h_qkvw[NLAY*3*DD*DD];
__device__ __half h_outw[NLAY*DD*DD];
__device__ __half h_ff1w[NLAY*DFFN*DD];
__device__ __half h_ff2w[NLAY*DD*DFFN];

__device__ __forceinline__ uint32_t smem_u32(const void* p) {
    uint32_t a;
    asm("{ .reg .u64 t; cvta.to.shared.u64 t, %1; cvt.u32.u64 %0, t; }"
        : "=r"(a) : "l"(p));
    return a;
}

__device__ __forceinline__ uint32_t packh2(float x, float y) {
    __half2 h = __floats2half2_rn(x, y);
    return *reinterpret_cast<uint32_t*>(&h);
}

__device__ __forceinline__ void ldsm_x4(uint32_t addr, uint32_t& r0, uint32_t& r1,
                                        uint32_t& r2, uint32_t& r3) {
    asm volatile("ldmatrix.sync.aligned.m8n8.x4.shared.b16 {%0,%1,%2,%3}, [%4];"
                 : "=r"(r0), "=r"(r1), "=r"(r2), "=r"(r3) : "r"(addr));
}

__device__ __forceinline__ void ldsm_x4_t(uint32_t addr, uint32_t& r0, uint32_t& r1,
                                          uint32_t& r2, uint32_t& r3) {
    asm volatile("ldmatrix.sync.aligned.m8n8.x4.trans.shared.b16 {%0,%1,%2,%3}, [%4];"
                 : "=r"(r0), "=r"(r1), "=r"(r2), "=r"(r3) : "r"(addr));
}

__device__ __forceinline__ void cpa16(uint32_t dst, const void* src, int src_sz) {
    asm volatile("cp.async.cg.shared.global [%0], [%1], 16, %2;"
                 :: "r"(dst), "l"(src), "r"(src_sz));
}
#define CP_COMMIT() asm volatile("cp.async.commit_group;" ::: "memory")
#define CP_WAIT1()  asm volatile("cp.async.wait_group 1;" ::: "memory")

#define MMA16816(d, a0,a1,a2,a3, b0,b1) \
    asm volatile( \
        "mma.sync.aligned.m16n8k16.row.col.f32.f16.f16.f32 " \
        "{%0,%1,%2,%3}, {%4,%5,%6,%7}, {%8,%9}, {%0,%1,%2,%3};\n" \
        : "+f"((d)[0]), "+f"((d)[1]), "+f"((d)[2]), "+f"((d)[3]) \
        : "r"(a0), "r"(a1), "r"(a2), "r"(a3), "r"(b0), "r"(b1))

// ---------------------------------------------------------------------------
// fp32 -> fp16 conversion (grid-stride, high MLP)
// ---------------------------------------------------------------------------
__global__ void f2h_kernel(const float4* __restrict__ s, uint2* __restrict__ d, int n4) {
    int stride = gridDim.x * blockDim.x;
    for (int i = blockIdx.x * blockDim.x + threadIdx.x; i < n4; i += stride) {
        float4 v = s[i];
        d[i] = make_uint2(packh2(v.x, v.y), packh2(v.z, v.w));
    }
}

// ---------------------------------------------------------------------------
// Meta + embedding
// ---------------------------------------------------------------------------
__global__ void meta_kernel(const int* __restrict__ ids, int* __restrict__ rel,
                            int* __restrict__ seg) {
    int b = blockIdx.x;
    if (threadIdx.x != 0) return;
    int last = 0, s = 0;
    for (int l = 0; l < LL; l++) {
        int id = ids[b*LL + l];
        if (id == EOS_ID) { last = l; s += 1; }
        rel[b*LL + l] = l - last;
        seg[b*LL + l] = s;
    }
}

__global__ void embed_kernel(const int* __restrict__ ids, const int* __restrict__ rel,
                             const float* __restrict__ tok, const float* __restrict__ pos,
                             float* __restrict__ x, __half* __restrict__ hx) {
    int row = blockIdx.x;
    int id = ids[row];
    int r  = rel[row];
    const float* t = tok + (size_t)id * DD;
    const float* p = pos + (size_t)r  * DD;
    const float sc = 27.712812921102035f;  // sqrt(768)
    for (int i = threadIdx.x; i < DD; i += blockDim.x) {
        float v = t[i] * sc + p[i];
        x[(size_t)row*DD + i]  = v;
        hx[(size_t)row*DD + i] = __float2half(v);
    }
}

#define HSTR 40   // halves per smem row (32 data + 8 pad); row stride 80 B
#define NS   3    // pipeline stages
#define GTILE (128*HSTR)                    // halves per (A or B) stage
#define GSMEM (NS*2*GTILE*2)                // bytes: 61440

// ---------------------------------------------------------------------------
// FP16 GEMM with cp.async 3-stage pipeline: C = A @ B^T (+bias)(+GELU)
// 128x128 tile, BK=32, 8 warps (4m x 2n), 32x64 warp tile, ldmatrix + mma.
// One __syncthreads per k-tile. OUTH -> fp16 C (N even). Grid x = M fast.
// ---------------------------------------------------------------------------
template<bool GELU, bool OUTH>
__global__ __launch_bounds__(256, 2)
void gemm_h(const __half* __restrict__ A, const __half* __restrict__ B,
            const float* __restrict__ bias, void* __restrict__ Cv,
            int M, int N, int K) {
    extern __shared__ __align__(16) __half GS[];
    const uint32_t sbase = smem_u32(GS);

    const int bm = blockIdx.x * 128;
    const int bn = blockIdx.y * 128;
    const int tid  = threadIdx.x;
    const int warp = tid >> 5;
    const int lane = tid & 31;
    const int grp  = lane >> 2;
    const int qid  = lane & 3;

    const int wm = (warp >> 1) * 32;
    const int wn = (warp & 1) * 64;

    const int lrow  = lane & 15;
    const int lcol8 = (lane >> 4) << 3;
    uint32_t aoff[2], boff[4];
#pragma unroll
    for (int i = 0; i < 2; i++)
        aoff[i] = ((wm + i*16 + lrow) * HSTR + lcol8) * 2;
#pragma unroll
    for (int p = 0; p < 4; p++)
        boff[p] = ((wn + p*16 + lrow) * HSTR + lcol8) * 2;

    // loader mapping: 512 16B-chunks per (A,B); 2 each per thread
    const int l_row = tid >> 1;          // 0..127
    const int l_c8a = (tid & 1) << 3;    // 0 or 8 (halves); +16 for second chunk
    const int gnB   = bn + l_row;
    const int gnBc  = gnB < N ? gnB : (N - 1);
    const int bsz   = gnB < N ? 16 : 0;
    const __half* Arow = A + (size_t)(bm + l_row) * K;
    const __half* Brow = B + (size_t)gnBc * K;

    float acc[2][8][4];
#pragma unroll
    for (int i = 0; i < 2; i++)
#pragma unroll
        for (int j = 0; j < 8; j++)
#pragma unroll
            for (int c = 0; c < 4; c++) acc[i][j][c] = 0.f;

    const int ntiles = K >> 5;

    // issue a tile's loads into stage s
    auto issue = [&](int t, int s) {
        int kt = t << 5;
        uint32_t sa = sbase + (s*GTILE + l_row*HSTR) * 2;
        uint32_t sb = sbase + ((NS + s)*GTILE + l_row*HSTR) * 2;
#pragma unroll
        for (int i = 0; i < 2; i++) {
            int c8 = l_c8a + i*16;
            cpa16(sa + c8*2, Arow + kt + c8, 16);
            cpa16(sb + c8*2, Brow + kt + c8, bsz);
        }
    };

    // prologue: tiles 0..NS-2
#pragma unroll
    for (int s = 0; s < NS-1; s++) { issue(s, s); CP_COMMIT(); }

    for (int t = 0; t < ntiles; t++) {
        CP_WAIT1();
        __syncthreads();

        if (t + NS - 1 < ntiles) issue(t + NS - 1, (t + NS - 1) % NS);
        CP_COMMIT();

        const int s = t % NS;
        const uint32_t sa = sbase + (s*GTILE) * 2;
        const uint32_t sb = sbase + ((NS + s)*GTILE) * 2;
#pragma unroll
        for (int ks = 0; ks < 2; ks++) {
            const uint32_t kb = ks * 32;
            uint32_t af[2][4];
#pragma unroll
            for (int i = 0; i < 2; i++)
                ldsm_x4(sa + aoff[i] + kb, af[i][0], af[i][1], af[i][2], af[i][3]);
#pragma unroll
            for (int p = 0; p < 4; p++) {
                uint32_t bf[4];
                ldsm_x4(sb + boff[p] + kb, bf[0], bf[1], bf[2], bf[3]);
#pragma unroll
                for (int i = 0; i < 2; i++) {
                    MMA16816(acc[i][2*p],   af[i][0], af[i][1], af[i][2], af[i][3], bf[0], bf[2]);
                    MMA16816(acc[i][2*p+1], af[i][0], af[i][1], af[i][2], af[i][3], bf[1], bf[3]);
                }
            }
        }
    }

    float*  Cf = reinterpret_cast<float*>(Cv);
    __half* Ch = reinterpret_cast<__half*>(Cv);
    const bool evenN = (N & 1) == 0;
#pragma unroll
    for (int i = 0; i < 2; i++) {
#pragma unroll
        for (int j = 0; j < 8; j++) {
#pragma unroll
            for (int pr = 0; pr < 2; pr++) {
                int row = bm + wm + i*16 + grp + pr*8;
                int col = bn + wn + j*8 + (qid << 1);
                float v0 = acc[i][j][2*pr + 0];
                float v1 = acc[i][j][2*pr + 1];
                if (bias) { v0 += bias[col]; if (col + 1 < N) v1 += bias[col + 1]; }
                if (GELU) {
                    v0 = 0.5f * v0 * (1.0f + erff(v0 * 0.7071067811865475f));
                    v1 = 0.5f * v1 * (1.0f + erff(v1 * 0.7071067811865475f));
                }
                size_t base = (size_t)row * N + col;
                if (OUTH) {
                    if (col + 1 < N) {
                        *reinterpret_cast<uint32_t*>(&Ch[base]) = packh2(v0, v1);
                    } else if (col < N) {
                        Ch[base] = __float2half(v0);
                    }
                } else {
                    if (col + 1 < N) {
                        if (evenN) *reinterpret_cast<float2*>(&Cf[base]) = make_float2(v0, v1);
                        else { Cf[base] = v0; Cf[base + 1] = v1; }
                    } else if (col < N) {
                        Cf[base] = v0;
                    }
                }
            }
        }
    }
}

// ---------------------------------------------------------------------------
// Tensor-core flash attention, fp16 qkv input (q-tile 128, kv-tile 64).
// ---------------------------------------------------------------------------
#define ASTR 72

__global__ __launch_bounds__(256, 2)
void attn_mma_kernel(const __half* __restrict__ qkv, const int* __restrict__ seg,
                     __half* __restrict__ o) {
    __shared__ __align__(16) __half Qh[128*ASTR];
    __shared__ __align__(16) __half Kh[64*ASTR];
    __shared__ __align__(16) __half Vh[64*ASTR];
    __shared__ int sseg[64];

    const int qt = blockIdx.x;
    const int h  = blockIdx.y;
    const int b  = blockIdx.z;
    const int tid  = threadIdx.x;
    const int warp = tid >> 5;
    const int lane = tid & 31;
    const int grp  = lane >> 2;
    const int qid  = lane & 3;
    const int q0 = qt * 128;

    const uint32_t qbase = smem_u32(Qh);
    const uint32_t kbase = smem_u32(Kh);
    const uint32_t vbase = smem_u32(Vh);
    const int lrow  = lane & 15;
    const int lcol8 = (lane >> 4) << 3;

    const __half2 sc2 = __floats2half2_rn(0.125f, 0.125f);
#pragma unroll
    for (int i = 0; i < 4; i++) {
        int idx = tid + (i << 8);
        int r  = idx >> 3;
        int c8 = (idx & 7) << 3;
        uint4 v = *reinterpret_cast<const uint4*>(
            qkv + (size_t)(b*LL + q0 + r)*(3*DD) + h*HD + c8);
        __half2* hv = reinterpret_cast<__half2*>(&v);
#pragma unroll
        for (int c = 0; c < 4; c++) hv[c] = __hmul2(hv[c], sc2);
        *reinterpret_cast<uint4*>(&Qh[r*ASTR + c8]) = v;
    }

    const int qg0 = q0 + warp*16 + grp;
    const int qg1 = qg0 + 8;
    const int qseg0 = seg[b*LL + qg0];
    const int qseg1 = seg[b*LL + qg1];

    float m0 = -1e30f, m1 = -1e30f, l0 = 0.f, l1 = 0.f;
    float O[8][4];
#pragma unroll
    for (int j = 0; j < 8; j++)
#pragma unroll
        for (int c = 0; c < 4; c++) O[j][c] = 0.f;

    const int ntiles = 2*qt + 2;
    for (int kt = 0; kt < ntiles; kt++) {
        const int k0 = kt * 64;
        __syncthreads();
#pragma unroll
        for (int i = 0; i < 2; i++) {
            int idx = tid + (i << 8);
            int r  = idx >> 3;
            int c8 = (idx & 7) << 3;
            const __half* base = qkv + (size_t)(b*LL + k0 + r)*(3*DD) + h*HD + c8;
            *reinterpret_cast<uint4*>(&Kh[r*ASTR + c8]) =
                *reinterpret_cast<const uint4*>(base + DD);
            *reinterpret_cast<uint4*>(&Vh[r*ASTR + c8]) =
                *reinterpret_cast<const uint4*>(base + 2*DD);
        }
        if (tid < 64) sseg[tid] = seg[b*LL + k0 + tid];
        __syncthreads();

        float s[8][4];
#pragma unroll
        for (int j = 0; j < 8; j++)
#pragma unroll
            for (int c = 0; c < 4; c++) s[j][c] = 0.f;
#pragma unroll
        for (int ks = 0; ks < 4; ks++) {
            uint32_t aq[4];
            ldsm_x4(qbase + ((warp*16 + lrow)*ASTR + ks*16 + lcol8)*2,
                    aq[0], aq[1], aq[2], aq[3]);
#pragma unroll
            for (int p = 0; p < 4; p++) {
                uint32_t bf[4];
                ldsm_x4(kbase + ((p*16 + lrow)*ASTR + ks*16 + lcol8)*2,
                        bf[0], bf[1], bf[2], bf[3]);
                MMA16816(s[2*p],   aq[0], aq[1], aq[2], aq[3], bf[0], bf[2]);
                MMA16816(s[2*p+1], aq[0], aq[1], aq[2], aq[3], bf[1], bf[3]);
            }
        }

        float mt0 = -1e30f, mt1 = -1e30f;
#pragma unroll
        for (int j = 0; j < 8; j++) {
            int kg0 = k0 + 8*j + 2*qid;
            int sg0 = sseg[8*j + 2*qid];
            int sg1 = sseg[8*j + 2*qid + 1];
            s[j][0] = (kg0     <= qg0 && sg0 == qseg0) ? s[j][0] : -1e30f;
            s[j][1] = (kg0 + 1 <= qg0 && sg1 == qseg0) ? s[j][1] : -1e30f;
            s[j][2] = (kg0     <= qg1 && sg0 == qseg1) ? s[j][2] : -1e30f;
            s[j][3] = (kg0 + 1 <= qg1 && sg1 == qseg1) ? s[j][3] : -1e30f;
            mt0 = fmaxf(mt0, fmaxf(s[j][0], s[j][1]));
            mt1 = fmaxf(mt1, fmaxf(s[j][2], s[j][3]));
        }
#pragma unroll
        for (int off = 1; off < 4; off <<= 1) {
            mt0 = fmaxf(mt0, __shfl_xor_sync(0xffffffffu, mt0, off));
            mt1 = fmaxf(mt1, __shfl_xor_sync(0xffffffffu, mt1, off));
        }
        float mn0 = fmaxf(m0, mt0), mn1 = fmaxf(m1, mt1);
        float f0 = __expf(m0 - mn0), f1 = __expf(m1 - mn1);
        m0 = mn0; m1 = mn1;
        float rs0 = 0.f, rs1 = 0.f;
#pragma unroll
        for (int j = 0; j < 8; j++) {
            s[j][0] = __expf(s[j][0] - mn0);
            s[j][1] = __expf(s[j][1] - mn0);
            s[j][2] = __expf(s[j][2] - mn1);
            s[j][3] = __expf(s[j][3] - mn1);
            rs0 += s[j][0] + s[j][1];
            rs1 += s[j][2] + s[j][3];
            O[j][0] *= f0; O[j][1] *= f0;
            O[j][2] *= f1; O[j][3] *= f1;
        }
#pragma unroll
        for (int off = 1; off < 4; off <<= 1) {
            rs0 += __shfl_xor_sync(0xffffffffu, rs0, off);
            rs1 += __shfl_xor_sync(0xffffffffu, rs1, off);
        }
        l0 = l0 * f0 + rs0;
        l1 = l1 * f1 + rs1;

        uint32_t ap[4][4];
#pragma unroll
        for (int ks = 0; ks < 4; ks++) {
            ap[ks][0] = packh2(s[2*ks][0],   s[2*ks][1]);
            ap[ks][1] = packh2(s[2*ks][2],   s[2*ks][3]);
            ap[ks][2] = packh2(s[2*ks+1][0], s[2*ks+1][1]);
            ap[ks][3] = packh2(s[2*ks+1][2], s[2*ks+1][3]);
        }

#pragma unroll
        for (int ks = 0; ks < 4; ks++) {
#pragma unroll
            for (int p = 0; p < 4; p++) {
                uint32_t bv[4];
                ldsm_x4_t(vbase + ((ks*16 + lrow)*ASTR + p*16 + lcol8)*2,
                          bv[0], bv[1], bv[2], bv[3]);
                MMA16816(O[2*p],   ap[ks][0], ap[ks][1], ap[ks][2], ap[ks][3], bv[0], bv[1]);
                MMA16816(O[2*p+1], ap[ks][0], ap[ks][1], ap[ks][2], ap[ks][3], bv[2], bv[3]);
            }
        }
    }

    float inv0 = 1.0f / l0, inv1 = 1.0f / l1;
#pragma unroll
    for (int j = 0; j < 8; j++) {
        int col = h*HD + 8*j + 2*qid;
        *reinterpret_cast<uint32_t*>(&o[(size_t)(b*LL + qg0)*DD + col]) =
            packh2(O[j][0]*inv0, O[j][1]*inv0);
        *reinterpret_cast<uint32_t*>(&o[(size_t)(b*LL + qg1)*DD + col]) =
            packh2(O[j][2]*inv1, O[j][3]*inv1);
    }
}

// ---------------------------------------------------------------------------
// Block reduction + fused add+LN
// ---------------------------------------------------------------------------
__device__ __forceinline__ float block_sum256(float v, volatile float* red) {
#pragma unroll
    for (int o = 16; o; o >>= 1) v += __shfl_xor_sync(0xffffffffu, v, o);
    if ((threadIdx.x & 31) == 0) red[threadIdx.x >> 5] = v;
    __syncthreads();
    if (threadIdx.x == 0) {
        float s = red[0];
#pragma unroll
        for (int i = 1; i < 8; i++) s += red[i];
        red[0] = s;
    }
    __syncthreads();
    float r = red[0];
    __syncthreads();
    return r;
}

__global__ __launch_bounds__(256)
void add_ln_kernel(float* __restrict__ x, const float* __restrict__ r,
                   const float* __restrict__ w, const float* __restrict__ b,
                   __half* __restrict__ hx) {
    int row = blockIdx.x;
    int tid = threadIdx.x;
    __shared__ float buf[DD];
    __shared__ float red[8];

    float s = 0.f;
    for (int i = tid; i < DD; i += 256) {
        float v = x[(size_t)row*DD + i] + r[(size_t)row*DD + i];
        buf[i] = v;
        s += v;
    }
    __syncthreads();
    float mean = block_sum256(s, red) * (1.0f / DD);

    float vs = 0.f;
    for (int i = tid; i < DD; i += 256) {
        float d = buf[i] - mean;
        vs += d * d;
    }
    float var = block_sum256(vs, red) * (1.0f / DD);
    float inv = rsqrtf(var + 1e-5f);

    for (int i = tid; i < DD; i += 256) {
        float v = (buf[i] - mean) * inv * w[i] + b[i];
        x[(size_t)row*DD + i]  = v;
        hx[(size_t)row*DD + i] = __float2half(v);
    }
}

// ---------------------------------------------------------------------------
// Host launcher
// ---------------------------------------------------------------------------
static inline void conv(const float* s, __half* d, long n) {
    int n4 = (int)(n / 4);
    int blocks = (n4 + 255) / 256;
    if (blocks > 1184) blocks = 1184;   // 148 SMs x 8 blocks
    f2h_kernel<<<blocks, 256>>>((const float4*)s, (uint2*)d, n4);
}

extern "C" void kernel_launch(void* const* d_in, const int* in_sizes, int n_in,
                              void* d_out, int out_size) {
    const int*   ids   = (const int*)  d_in[0];
    const float* tok   = (const float*)d_in[1];
    const float* pos   = (const float*)d_in[2];
    const float* qkv_w = (const float*)d_in[3];
    const float* qkv_b = (const float*)d_in[4];
    const float* out_w = (const float*)d_in[5];
    const float* out_b = (const float*)d_in[6];
    const float* ln1_w = (const float*)d_in[7];
    const float* ln1_b = (const float*)d_in[8];
    const float* ln2_w = (const float*)d_in[9];
    const float* ln2_b = (const float*)d_in[10];
    const float* ff1_w = (const float*)d_in[11];
    const float* ff1_b = (const float*)d_in[12];
    const float* ff2_w = (const float*)d_in[13];
    const float* ff2_b = (const float*)d_in[14];
    float* out = (float*)d_out;

    float *x, *tmp;
    int *rel, *seg;
    __half *hqkv, *hx, *hatt, *hff, *htok, *hqkvw, *houtw, *hff1w, *hff2w;
    cudaGetSymbolAddress((void**)&x,    g_x);
    cudaGetSymbolAddress((void**)&tmp,  g_tmp);
    cudaGetSymbolAddress((void**)&rel,  g_rel);
    cudaGetSymbolAddress((void**)&seg,  g_seg);
    cudaGetSymbolAddress((void**)&hqkv, h_qkv);
    cudaGetSymbolAddress((void**)&hx,   h_x);
    cudaGetSymbolAddress((void**)&hatt, h_att);
    cudaGetSymbolAddress((void**)&hff,  h_ff);
    cudaGetSymbolAddress((void**)&htok, h_tok);
    cudaGetSymbolAddress((void**)&hqkvw, h_qkvw);
    cudaGetSymbolAddress((void**)&houtw, h_outw);
    cudaGetSymbolAddress((void**)&hff1w, h_ff1w);
    cudaGetSymbolAddress((void**)&hff2w, h_ff2w);

    cudaFuncSetAttribute(gemm_h<false,false>,
        cudaFuncAttributeMaxDynamicSharedMemorySize, GSMEM);
    cudaFuncSetAttribute(gemm_h<false,true>,
        cudaFuncAttributeMaxDynamicSharedMemorySize, GSMEM);
    cudaFuncSetAttribute(gemm_h<true,true>,
        cudaFuncAttributeMaxDynamicSharedMemorySize, GSMEM);

    conv(tok,   htok,  (long)VV*DD);
    conv(qkv_w, hqkvw, (long)NLAY*3*DD*DD);
    conv(out_w, houtw, (long)NLAY*DD*DD);
    conv(ff1_w, hff1w, (long)NLAY*DFFN*DD);
    conv(ff2_w, hff2w, (long)NLAY*DD*DFFN);

    meta_kernel<<<BB, 32>>>(ids, rel, seg);
    embed_kernel<<<ROWS, 256>>>(ids, rel, tok, pos, x, hx);

    const int MT = ROWS / 128;

    for (int l = 0; l < NLAY; l++) {
        gemm_h<false,true><<<dim3(MT, 3*DD/128), 256, GSMEM>>>(
            hx, hqkvw + (size_t)l*3*DD*DD, qkv_b + (size_t)l*3*DD, hqkv,
            ROWS, 3*DD, DD);

        attn_mma_kernel<<<dim3(LL/128, HH, BB), 256>>>(hqkv, seg, hatt);

        gemm_h<false,false><<<dim3(MT, DD/128), 256, GSMEM>>>(
            hatt, houtw + (size_t)l*DD*DD, out_b + (size_t)l*DD, tmp,
            ROWS, DD, DD);

        add_ln_kernel<<<ROWS, 256>>>(x, tmp, ln1_w + (size_t)l*DD, ln1_b + (size_t)l*DD, hx);

        gemm_h<true,true><<<dim3(MT, DFFN/128), 256, GSMEM>>>(
            hx, hff1w + (size_t)l*DFFN*DD, ff1_b + (size_t)l*DFFN, hff,
            ROWS, DFFN, DD);

        gemm_h<false,false><<<dim3(MT, DD/128), 256, GSMEM>>>(
            hff, hff2w + (size_t)l*DD*DFFN, ff2_b + (size_t)l*DD, tmp,
            ROWS, DD, DFFN);

        add_ln_kernel<<<ROWS, 256>>>(x, tmp, ln2_w + (size_t)l*DD, ln2_b + (size_t)l*DD, hx);
    }

    gemm_h<false,false><<<dim3(MT, (VV + 127)/128), 256, GSMEM>>>(
        hx, htok, nullptr, out, ROWS, VV, DD);
}

// round 14
// speedup vs baseline: 1.0478x; 1.0478x over previous
#include <cuda_runtime.h>
#include <cuda_fp16.h>
#include <math.h>
#include <stdint.h>

// Problem constants
#define BB   2
#define LL   1024
#define DD   768
#define HH   12
#define HD   64
#define NLAY 2
#define DFFN 3072
#define VV   50257
#define EOS_ID 50256
#define ROWS (BB*LL)          // 2048

// ---------------------------------------------------------------------------
// Static scratch
// ---------------------------------------------------------------------------
__device__ float  g_x[ROWS*DD];
__device__ float  g_tmp[ROWS*DD];
__device__ int    g_rel[ROWS];
__device__ int    g_seg[ROWS];
// fp16 tensors
__device__ __half h_qkv[ROWS*3*DD];
__device__ __half h_x[ROWS*DD];
__device__ __half h_att[ROWS*DD];
__device__ __half h_ff[ROWS*DFFN];
__device__ __half h_tok[VV*DD];
__device__ __half h_qkvw[NLAY*3*DD*DD];
__device__ __half h_outw[NLAY*DD*DD];
__device__ __half h_ff1w[NLAY*DFFN*DD];
__device__ __half h_ff2w[NLAY*DD*DFFN];

__device__ __forceinline__ uint32_t smem_u32(const void* p) {
    uint32_t a;
    asm("{ .reg .u64 t; cvta.to.shared.u64 t, %1; cvt.u32.u64 %0, t; }"
        : "=r"(a) : "l"(p));
    return a;
}

__device__ __forceinline__ uint32_t packh2(float x, float y) {
    __half2 h = __floats2half2_rn(x, y);
    return *reinterpret_cast<uint32_t*>(&h);
}

__device__ __forceinline__ void ldsm_x4(uint32_t addr, uint32_t& r0, uint32_t& r1,
                                        uint32_t& r2, uint32_t& r3) {
    asm volatile("ldmatrix.sync.aligned.m8n8.x4.shared.b16 {%0,%1,%2,%3}, [%4];"
                 : "=r"(r0), "=r"(r1), "=r"(r2), "=r"(r3) : "r"(addr));
}

__device__ __forceinline__ void ldsm_x4_t(uint32_t addr, uint32_t& r0, uint32_t& r1,
                                          uint32_t& r2, uint32_t& r3) {
    asm volatile("ldmatrix.sync.aligned.m8n8.x4.trans.shared.b16 {%0,%1,%2,%3}, [%4];"
                 : "=r"(r0), "=r"(r1), "=r"(r2), "=r"(r3) : "r"(addr));
}

#define MMA16816(d, a0,a1,a2,a3, b0,b1) \
    asm volatile( \
        "mma.sync.aligned.m16n8k16.row.col.f32.f16.f16.f32 " \
        "{%0,%1,%2,%3}, {%4,%5,%6,%7}, {%8,%9}, {%0,%1,%2,%3};\n" \
        : "+f"((d)[0]), "+f"((d)[1]), "+f"((d)[2]), "+f"((d)[3]) \
        : "r"(a0), "r"(a1), "r"(a2), "r"(a3), "r"(b0), "r"(b1))

// ---------------------------------------------------------------------------
// fp32 -> fp16 conversion v3: 32B read + 16B store per thread (n % 8 == 0)
// ---------------------------------------------------------------------------
__global__ void f2h_kernel(const float4* __restrict__ s, uint4* __restrict__ d, int n8) {
    int i = blockIdx.x * blockDim.x + threadIdx.x;
    if (i < n8) {
        float4 a = s[2*i];
        float4 b = s[2*i + 1];
        d[i] = make_uint4(packh2(a.x, a.y), packh2(a.z, a.w),
                          packh2(b.x, b.y), packh2(b.z, b.w));
    }
}

// ---------------------------------------------------------------------------
// Meta + embedding
// ---------------------------------------------------------------------------
__global__ void meta_kernel(const int* __restrict__ ids, int* __restrict__ rel,
                            int* __restrict__ seg) {
    int b = blockIdx.x;
    if (threadIdx.x != 0) return;
    int last = 0, s = 0;
    for (int l = 0; l < LL; l++) {
        int id = ids[b*LL + l];
        if (id == EOS_ID) { last = l; s += 1; }
        rel[b*LL + l] = l - last;
        seg[b*LL + l] = s;
    }
}

__global__ void embed_kernel(const int* __restrict__ ids, const int* __restrict__ rel,
                             const float* __restrict__ tok, const float* __restrict__ pos,
                             float* __restrict__ x, __half* __restrict__ hx) {
    int row = blockIdx.x;
    int id = ids[row];
    int r  = rel[row];
    const float* t = tok + (size_t)id * DD;
    const float* p = pos + (size_t)r  * DD;
    const float sc = 27.712812921102035f;  // sqrt(768)
    for (int i = threadIdx.x; i < DD; i += blockDim.x) {
        float v = t[i] * sc + p[i];
        x[(size_t)row*DD + i]  = v;
        hx[(size_t)row*DD + i] = __float2half(v);
    }
}

#define HSTR 40   // halves per smem row for GEMM (32 data + 8 pad)

// ---------------------------------------------------------------------------
// FP16-operand GEMM (R11): C = A @ B^T (+bias)(+GELU). OUTH -> fp16 C (N even).
// 128x128 tile, BK=32, 8 warps (4m x 2n), 32x64 warp tile, ldmatrix + m16n8k16.
// ---------------------------------------------------------------------------
template<bool GELU, bool OUTH>
__global__ __launch_bounds__(256, 2)
void gemm_h(const __half* __restrict__ A, const __half* __restrict__ B,
            const float* __restrict__ bias, void* __restrict__ Cv,
            int M, int N, int K) {
    __shared__ __align__(16) __half SA[2][128*HSTR];
    __shared__ __align__(16) __half SB[2][128*HSTR];

    const int bm = blockIdx.x * 128;
    const int bn = blockIdx.y * 128;
    const int tid  = threadIdx.x;
    const int warp = tid >> 5;
    const int lane = tid & 31;
    const int grp  = lane >> 2;
    const int qid  = lane & 3;

    const int wm = (warp >> 1) * 32;
    const int wn = (warp & 1) * 64;

    const int lrow  = lane & 15;
    const int lcol8 = (lane >> 4) << 3;
    uint32_t aoff[2], boff[4];
#pragma unroll
    for (int i = 0; i < 2; i++)
        aoff[i] = ((wm + i*16 + lrow) * HSTR + lcol8) * 2;
#pragma unroll
    for (int p = 0; p < 4; p++)
        boff[p] = ((wn + p*16 + lrow) * HSTR + lcol8) * 2;

    const uint32_t sa0 = smem_u32(&SA[0][0]), sa1 = smem_u32(&SA[1][0]);
    const uint32_t sb0 = smem_u32(&SB[0][0]), sb1 = smem_u32(&SB[1][0]);

    float acc[2][8][4];
#pragma unroll
    for (int i = 0; i < 2; i++)
#pragma unroll
        for (int j = 0; j < 8; j++)
#pragma unroll
            for (int c = 0; c < 4; c++) acc[i][j][c] = 0.f;

    const int ntiles = K >> 5;
    uint4 rA[2], rB[2];
    const uint4 zero4 = make_uint4(0u, 0u, 0u, 0u);

#pragma unroll
    for (int i = 0; i < 2; i++) {
        int idx = tid + (i << 8);
        int row = idx >> 2;
        int s8  = (idx & 3) << 3;
        rA[i] = *reinterpret_cast<const uint4*>(A + (size_t)(bm + row) * K + s8);
        int gn = bn + row;
        rB[i] = (gn < N) ? *reinterpret_cast<const uint4*>(B + (size_t)gn * K + s8)
                         : zero4;
    }
#pragma unroll
    for (int i = 0; i < 2; i++) {
        int idx = tid + (i << 8);
        int row = idx >> 2;
        int s8  = (idx & 3) << 3;
        *reinterpret_cast<uint4*>(&SA[0][row*HSTR + s8]) = rA[i];
        *reinterpret_cast<uint4*>(&SB[0][row*HSTR + s8]) = rB[i];
    }
    __syncthreads();

    for (int t = 0; t < ntiles; t++) {
        const int cb = t & 1;
        const bool more = (t + 1 < ntiles);

        if (more) {
            int kt = (t + 1) << 5;
#pragma unroll
            for (int i = 0; i < 2; i++) {
                int idx = tid + (i << 8);
                int row = idx >> 2;
                int s8  = (idx & 3) << 3;
                rA[i] = *reinterpret_cast<const uint4*>(A + (size_t)(bm + row) * K + kt + s8);
                int gn = bn + row;
                rB[i] = (gn < N) ? *reinterpret_cast<const uint4*>(B + (size_t)gn * K + kt + s8)
                                 : zero4;
            }
        }

        const uint32_t sa = cb ? sa1 : sa0;
        const uint32_t sb = cb ? sb1 : sb0;
#pragma unroll
        for (int ks = 0; ks < 2; ks++) {
            const uint32_t kb = ks * 32;
            uint32_t af[2][4];
#pragma unroll
            for (int i = 0; i < 2; i++)
                ldsm_x4(sa + aoff[i] + kb, af[i][0], af[i][1], af[i][2], af[i][3]);
#pragma unroll
            for (int p = 0; p < 4; p++) {
                uint32_t bf[4];
                ldsm_x4(sb + boff[p] + kb, bf[0], bf[1], bf[2], bf[3]);
#pragma unroll
                for (int i = 0; i < 2; i++) {
                    MMA16816(acc[i][2*p],   af[i][0], af[i][1], af[i][2], af[i][3], bf[0], bf[2]);
                    MMA16816(acc[i][2*p+1], af[i][0], af[i][1], af[i][2], af[i][3], bf[1], bf[3]);
                }
            }
        }

        if (more) {
            const int nb = (t + 1) & 1;
#pragma unroll
            for (int i = 0; i < 2; i++) {
                int idx = tid + (i << 8);
                int row = idx >> 2;
                int s8  = (idx & 3) << 3;
                *reinterpret_cast<uint4*>(&SA[nb][row*HSTR + s8]) = rA[i];
                *reinterpret_cast<uint4*>(&SB[nb][row*HSTR + s8]) = rB[i];
            }
        }
        __syncthreads();
    }

    float*  Cf = reinterpret_cast<float*>(Cv);
    __half* Ch = reinterpret_cast<__half*>(Cv);
    const bool evenN = (N & 1) == 0;
#pragma unroll
    for (int i = 0; i < 2; i++) {
#pragma unroll
        for (int j = 0; j < 8; j++) {
#pragma unroll
            for (int pr = 0; pr < 2; pr++) {
                int row = bm + wm + i*16 + grp + pr*8;
                int col = bn + wn + j*8 + (qid << 1);
                float v0 = acc[i][j][2*pr + 0];
                float v1 = acc[i][j][2*pr + 1];
                if (bias) { v0 += bias[col]; if (col + 1 < N) v1 += bias[col + 1]; }
                if (GELU) {
                    v0 = 0.5f * v0 * (1.0f + erff(v0 * 0.7071067811865475f));
                    v1 = 0.5f * v1 * (1.0f + erff(v1 * 0.7071067811865475f));
                }
                size_t base = (size_t)row * N + col;
                if (OUTH) {
                    if (col + 1 < N) {
                        *reinterpret_cast<uint32_t*>(&Ch[base]) = packh2(v0, v1);
                    } else if (col < N) {
                        Ch[base] = __float2half(v0);
                    }
                } else {
                    if (col + 1 < N) {
                        if (evenN) *reinterpret_cast<float2*>(&Cf[base]) = make_float2(v0, v1);
                        else { Cf[base] = v0; Cf[base + 1] = v1; }
                    } else if (col < N) {
                        Cf[base] = v0;
                    }
                }
            }
        }
    }
}

// ---------------------------------------------------------------------------
// Tensor-core flash attention, fp16 qkv input (q-tile 128, kv-tile 64). (R11)
// ---------------------------------------------------------------------------
#define ASTR 72

__global__ __launch_bounds__(256, 2)
void attn_mma_kernel(const __half* __restrict__ qkv, const int* __restrict__ seg,
                     __half* __restrict__ o) {
    __shared__ __align__(16) __half Qh[128*ASTR];
    __shared__ __align__(16) __half Kh[64*ASTR];
    __shared__ __align__(16) __half Vh[64*ASTR];
    __shared__ int sseg[64];

    const int qt = blockIdx.x;
    const int h  = blockIdx.y;
    const int b  = blockIdx.z;
    const int tid  = threadIdx.x;
    const int warp = tid >> 5;
    const int lane = tid & 31;
    const int grp  = lane >> 2;
    const int qid  = lane & 3;
    const int q0 = qt * 128;

    const uint32_t qbase = smem_u32(Qh);
    const uint32_t kbase = smem_u32(Kh);
    const uint32_t vbase = smem_u32(Vh);
    const int lrow  = lane & 15;
    const int lcol8 = (lane >> 4) << 3;

    const __half2 sc2 = __floats2half2_rn(0.125f, 0.125f);
#pragma unroll
    for (int i = 0; i < 4; i++) {
        int idx = tid + (i << 8);
        int r  = idx >> 3;
        int c8 = (idx & 7) << 3;
        uint4 v = *reinterpret_cast<const uint4*>(
            qkv + (size_t)(b*LL + q0 + r)*(3*DD) + h*HD + c8);
        __half2* hv = reinterpret_cast<__half2*>(&v);
#pragma unroll
        for (int c = 0; c < 4; c++) hv[c] = __hmul2(hv[c], sc2);
        *reinterpret_cast<uint4*>(&Qh[r*ASTR + c8]) = v;
    }

    const int qg0 = q0 + warp*16 + grp;
    const int qg1 = qg0 + 8;
    const int qseg0 = seg[b*LL + qg0];
    const int qseg1 = seg[b*LL + qg1];

    float m0 = -1e30f, m1 = -1e30f, l0 = 0.f, l1 = 0.f;
    float O[8][4];
#pragma unroll
    for (int j = 0; j < 8; j++)
#pragma unroll
        for (int c = 0; c < 4; c++) O[j][c] = 0.f;

    const int ntiles = 2*qt + 2;
    for (int kt = 0; kt < ntiles; kt++) {
        const int k0 = kt * 64;
        __syncthreads();
#pragma unroll
        for (int i = 0; i < 2; i++) {
            int idx = tid + (i << 8);
            int r  = idx >> 3;
            int c8 = (idx & 7) << 3;
            const __half* base = qkv + (size_t)(b*LL + k0 + r)*(3*DD) + h*HD + c8;
            *reinterpret_cast<uint4*>(&Kh[r*ASTR + c8]) =
                *reinterpret_cast<const uint4*>(base + DD);
            *reinterpret_cast<uint4*>(&Vh[r*ASTR + c8]) =
                *reinterpret_cast<const uint4*>(base + 2*DD);
        }
        if (tid < 64) sseg[tid] = seg[b*LL + k0 + tid];
        __syncthreads();

        float s[8][4];
#pragma unroll
        for (int j = 0; j < 8; j++)
#pragma unroll
            for (int c = 0; c < 4; c++) s[j][c] = 0.f;
#pragma unroll
        for (int ks = 0; ks < 4; ks++) {
            uint32_t aq[4];
            ldsm_x4(qbase + ((warp*16 + lrow)*ASTR + ks*16 + lcol8)*2,
                    aq[0], aq[1], aq[2], aq[3]);
#pragma unroll
            for (int p = 0; p < 4; p++) {
                uint32_t bf[4];
                ldsm_x4(kbase + ((p*16 + lrow)*ASTR + ks*16 + lcol8)*2,
                        bf[0], bf[1], bf[2], bf[3]);
                MMA16816(s[2*p],   aq[0], aq[1], aq[2], aq[3], bf[0], bf[2]);
                MMA16816(s[2*p+1], aq[0], aq[1], aq[2], aq[3], bf[1], bf[3]);
            }
        }

        float mt0 = -1e30f, mt1 = -1e30f;
#pragma unroll
        for (int j = 0; j < 8; j++) {
            int kg0 = k0 + 8*j + 2*qid;
            int sg0 = sseg[8*j + 2*qid];
            int sg1 = sseg[8*j + 2*qid + 1];
            s[j][0] = (kg0     <= qg0 && sg0 == qseg0) ? s[j][0] : -1e30f;
            s[j][1] = (kg0 + 1 <= qg0 && sg1 == qseg0) ? s[j][1] : -1e30f;
            s[j][2] = (kg0     <= qg1 && sg0 == qseg1) ? s[j][2] : -1e30f;
            s[j][3] = (kg0 + 1 <= qg1 && sg1 == qseg1) ? s[j][3] : -1e30f;
            mt0 = fmaxf(mt0, fmaxf(s[j][0], s[j][1]));
            mt1 = fmaxf(mt1, fmaxf(s[j][2], s[j][3]));
        }
#pragma unroll
        for (int off = 1; off < 4; off <<= 1) {
            mt0 = fmaxf(mt0, __shfl_xor_sync(0xffffffffu, mt0, off));
            mt1 = fmaxf(mt1, __shfl_xor_sync(0xffffffffu, mt1, off));
        }
        float mn0 = fmaxf(m0, mt0), mn1 = fmaxf(m1, mt1);
        float f0 = __expf(m0 - mn0), f1 = __expf(m1 - mn1);
        m0 = mn0; m1 = mn1;
        float rs0 = 0.f, rs1 = 0.f;
#pragma unroll
        for (int j = 0; j < 8; j++) {
            s[j][0] = __expf(s[j][0] - mn0);
            s[j][1] = __expf(s[j][1] - mn0);
            s[j][2] = __expf(s[j][2] - mn1);
            s[j][3] = __expf(s[j][3] - mn1);
            rs0 += s[j][0] + s[j][1];
            rs1 += s[j][2] + s[j][3];
            O[j][0] *= f0; O[j][1] *= f0;
            O[j][2] *= f1; O[j][3] *= f1;
        }
#pragma unroll
        for (int off = 1; off < 4; off <<= 1) {
            rs0 += __shfl_xor_sync(0xffffffffu, rs0, off);
            rs1 += __shfl_xor_sync(0xffffffffu, rs1, off);
        }
        l0 = l0 * f0 + rs0;
        l1 = l1 * f1 + rs1;

        uint32_t ap[4][4];
#pragma unroll
        for (int ks = 0; ks < 4; ks++) {
            ap[ks][0] = packh2(s[2*ks][0],   s[2*ks][1]);
            ap[ks][1] = packh2(s[2*ks][2],   s[2*ks][3]);
            ap[ks][2] = packh2(s[2*ks+1][0], s[2*ks+1][1]);
            ap[ks][3] = packh2(s[2*ks+1][2], s[2*ks+1][3]);
        }

#pragma unroll
        for (int ks = 0; ks < 4; ks++) {
#pragma unroll
            for (int p = 0; p < 4; p++) {
                uint32_t bv[4];
                ldsm_x4_t(vbase + ((ks*16 + lrow)*ASTR + p*16 + lcol8)*2,
                          bv[0], bv[1], bv[2], bv[3]);
                MMA16816(O[2*p],   ap[ks][0], ap[ks][1], ap[ks][2], ap[ks][3], bv[0], bv[1]);
                MMA16816(O[2*p+1], ap[ks][0], ap[ks][1], ap[ks][2], ap[ks][3], bv[2], bv[3]);
            }
        }
    }

    float inv0 = 1.0f / l0, inv1 = 1.0f / l1;
#pragma unroll
    for (int j = 0; j < 8; j++) {
        int col = h*HD + 8*j + 2*qid;
        *reinterpret_cast<uint32_t*>(&o[(size_t)(b*LL + qg0)*DD + col]) =
            packh2(O[j][0]*inv0, O[j][1]*inv0);
        *reinterpret_cast<uint32_t*>(&o[(size_t)(b*LL + qg1)*DD + col]) =
            packh2(O[j][2]*inv1, O[j][3]*inv1);
    }
}

// ---------------------------------------------------------------------------
// add+LN, warp-per-row: 8 rows per 256-thread block, shuffle-only reductions.
// ---------------------------------------------------------------------------
__global__ __launch_bounds__(256)
void add_ln_kernel(float* __restrict__ x, const float* __restrict__ r,
                   const float* __restrict__ w, const float* __restrict__ b,
                   __half* __restrict__ hx) {
    const int wid  = threadIdx.x >> 5;
    const int lane = threadIdx.x & 31;
    const int row  = blockIdx.x * 8 + wid;

    const float4* xr = reinterpret_cast<const float4*>(x + (size_t)row*DD);
    const float4* rr = reinterpret_cast<const float4*>(r + (size_t)row*DD);
    const float4* wr = reinterpret_cast<const float4*>(w);
    const float4* br = reinterpret_cast<const float4*>(b);

    float4 v[6];
    float s = 0.f;
#pragma unroll
    for (int j = 0; j < 6; j++) {
        float4 a = xr[lane + 32*j];
        float4 c = rr[lane + 32*j];
        a.x += c.x; a.y += c.y; a.z += c.z; a.w += c.w;
        v[j] = a;
        s += a.x + a.y + a.z + a.w;
    }
#pragma unroll
    for (int off = 16; off; off >>= 1) s += __shfl_xor_sync(0xffffffffu, s, off);
    const float mean = s * (1.0f / DD);

    float vs = 0.f;
#pragma unroll
    for (int j = 0; j < 6; j++) {
        float dx = v[j].x - mean, dy = v[j].y - mean;
        float dz = v[j].z - mean, dw = v[j].w - mean;
        vs += dx*dx + dy*dy + dz*dz + dw*dw;
    }
#pragma unroll
    for (int off = 16; off; off >>= 1) vs += __shfl_xor_sync(0xffffffffu, vs, off);
    const float inv = rsqrtf(vs * (1.0f / DD) + 1e-5f);

    float4* xo = reinterpret_cast<float4*>(x + (size_t)row*DD);
    uint2*  ho = reinterpret_cast<uint2*>(hx + (size_t)row*DD);
#pragma unroll
    for (int j = 0; j < 6; j++) {
        float4 ww = wr[lane + 32*j];
        float4 bb = br[lane + 32*j];
        float4 o;
        o.x = (v[j].x - mean) * inv * ww.x + bb.x;
        o.y = (v[j].y - mean) * inv * ww.y + bb.y;
        o.z = (v[j].z - mean) * inv * ww.z + bb.z;
        o.w = (v[j].w - mean) * inv * ww.w + bb.w;
        xo[lane + 32*j] = o;
        ho[lane + 32*j] = make_uint2(packh2(o.x, o.y), packh2(o.z, o.w));
    }
}

// ---------------------------------------------------------------------------
// Host launcher
// ---------------------------------------------------------------------------
static inline void conv(const float* s, __half* d, long n) {
    int n8 = (int)(n / 8);
    int blocks = (n8 + 255) / 256;
    f2h_kernel<<<blocks, 256>>>((const float4*)s, (uint4*)d, n8);
}

extern "C" void kernel_launch(void* const* d_in, const int* in_sizes, int n_in,
                              void* d_out, int out_size) {
    const int*   ids   = (const int*)  d_in[0];
    const float* tok   = (const float*)d_in[1];
    const float* pos   = (const float*)d_in[2];
    const float* qkv_w = (const float*)d_in[3];
    const float* qkv_b = (const float*)d_in[4];
    const float* out_w = (const float*)d_in[5];
    const float* out_b = (const float*)d_in[6];
    const float* ln1_w = (const float*)d_in[7];
    const float* ln1_b = (const float*)d_in[8];
    const float* ln2_w = (const float*)d_in[9];
    const float* ln2_b = (const float*)d_in[10];
    const float* ff1_w = (const float*)d_in[11];
    const float* ff1_b = (const float*)d_in[12];
    const float* ff2_w = (const float*)d_in[13];
    const float* ff2_b = (const float*)d_in[14];
    float* out = (float*)d_out;

    float *x, *tmp;
    int *rel, *seg;
    __half *hqkv, *hx, *hatt, *hff, *htok, *hqkvw, *houtw, *hff1w, *hff2w;
    cudaGetSymbolAddress((void**)&x,    g_x);
    cudaGetSymbolAddress((void**)&tmp,  g_tmp);
    cudaGetSymbolAddress((void**)&rel,  g_rel);
    cudaGetSymbolAddress((void**)&seg,  g_seg);
    cudaGetSymbolAddress((void**)&hqkv, h_qkv);
    cudaGetSymbolAddress((void**)&hx,   h_x);
    cudaGetSymbolAddress((void**)&hatt, h_att);
    cudaGetSymbolAddress((void**)&hff,  h_ff);
    cudaGetSymbolAddress((void**)&htok, h_tok);
    cudaGetSymbolAddress((void**)&hqkvw, h_qkvw);
    cudaGetSymbolAddress((void**)&houtw, h_outw);
    cudaGetSymbolAddress((void**)&hff1w, h_ff1w);
    cudaGetSymbolAddress((void**)&hff2w, h_ff2w);

    // operand conversions (deterministic, every launch)
    conv(tok,   htok,  (long)VV*DD);
    conv(qkv_w, hqkvw, (long)NLAY*3*DD*DD);
    conv(out_w, houtw, (long)NLAY*DD*DD);
    conv(ff1_w, hff1w, (long)NLAY*DFFN*DD);
    conv(ff2_w, hff2w, (long)NLAY*DD*DFFN);

    meta_kernel<<<BB, 32>>>(ids, rel, seg);
    embed_kernel<<<ROWS, 256>>>(ids, rel, tok, pos, x, hx);

    const int MT = ROWS / 128;  // 16, fast axis

    for (int l = 0; l < NLAY; l++) {
        gemm_h<false,true><<<dim3(MT, 3*DD/128), 256>>>(
            hx, hqkvw + (size_t)l*3*DD*DD, qkv_b + (size_t)l*3*DD, hqkv,
            ROWS, 3*DD, DD);

        attn_mma_kernel<<<dim3(LL/128, HH, BB), 256>>>(hqkv, seg, hatt);

        gemm_h<false,false><<<dim3(MT, DD/128), 256>>>(
            hatt, houtw + (size_t)l*DD*DD, out_b + (size_t)l*DD, tmp,
            ROWS, DD, DD);

        add_ln_kernel<<<ROWS/8, 256>>>(x, tmp, ln1_w + (size_t)l*DD, ln1_b + (size_t)l*DD, hx);

        gemm_h<true,true><<<dim3(MT, DFFN/128), 256>>>(
            hx, hff1w + (size_t)l*DFFN*DD, ff1_b + (size_t)l*DFFN, hff,
            ROWS, DFFN, DD);

        gemm_h<false,false><<<dim3(MT, DD/128), 256>>>(
            hff, hff2w + (size_t)l*DD*DFFN, ff2_b + (size_t)l*DD, tmp,
            ROWS, DD, DFFN);

        add_ln_kernel<<<ROWS/8, 256>>>(x, tmp, ln2_w + (size_t)l*DD, ln2_b + (size_t)l*DD, hx);
    }

    gemm_h<false,false><<<dim3(MT, (VV + 127)/128), 256>>>(
        hx, htok, nullptr, out, ROWS, VV, DD);
}

// round 15
// speedup vs baseline: 1.0522x; 1.0041x over previous
#include <cuda_runtime.h>
#include <cuda_fp16.h>
#include <math.h>
#include <stdint.h>

// Problem constants
#define BB   2
#define LL   1024
#define DD   768
#define HH   12
#define HD   64
#define NLAY 2
#define DFFN 3072
#define VV   50257
#define EOS_ID 50256
#define ROWS (BB*LL)          // 2048

// ---------------------------------------------------------------------------
// Static scratch
// ---------------------------------------------------------------------------
__device__ float  g_x[ROWS*DD];
__device__ float  g_tmp[ROWS*DD];
__device__ int    g_rel[ROWS];
__device__ int    g_seg[ROWS];
// fp16 tensors
__device__ __half h_qkv[ROWS*3*DD];
__device__ __half h_x[ROWS*DD];
__device__ __half h_att[ROWS*DD];
__device__ __half h_ff[ROWS*DFFN];
__device__ __half h_tok[VV*DD];
__device__ __half h_qkvw[NLAY*3*DD*DD];
__device__ __half h_outw[NLAY*DD*DD];
__device__ __half h_ff1w[NLAY*DFFN*DD];
__device__ __half h_ff2w[NLAY*DD*DFFN];

__device__ __forceinline__ uint32_t smem_u32(const void* p) {
    uint32_t a;
    asm("{ .reg .u64 t; cvta.to.shared.u64 t, %1; cvt.u32.u64 %0, t; }"
        : "=r"(a) : "l"(p));
    return a;
}

__device__ __forceinline__ uint32_t packh2(float x, float y) {
    __half2 h = __floats2half2_rn(x, y);
    return *reinterpret_cast<uint32_t*>(&h);
}

__device__ __forceinline__ void ldsm_x4(uint32_t addr, uint32_t& r0, uint32_t& r1,
                                        uint32_t& r2, uint32_t& r3) {
    asm volatile("ldmatrix.sync.aligned.m8n8.x4.shared.b16 {%0,%1,%2,%3}, [%4];"
                 : "=r"(r0), "=r"(r1), "=r"(r2), "=r"(r3) : "r"(addr));
}

__device__ __forceinline__ void ldsm_x4_t(uint32_t addr, uint32_t& r0, uint32_t& r1,
                                          uint32_t& r2, uint32_t& r3) {
    asm volatile("ldmatrix.sync.aligned.m8n8.x4.trans.shared.b16 {%0,%1,%2,%3}, [%4];"
                 : "=r"(r0), "=r"(r1), "=r"(r2), "=r"(r3) : "r"(addr));
}

__device__ __forceinline__ void cpa16(uint32_t dst, const void* src) {
    asm volatile("cp.async.cg.shared.global [%0], [%1], 16;"
                 :: "r"(dst), "l"(src));
}
#define CP_COMMIT() asm volatile("cp.async.commit_group;" ::: "memory")
#define CP_WAIT0()  asm volatile("cp.async.wait_group 0;" ::: "memory")
#define CP_WAIT1()  asm volatile("cp.async.wait_group 1;" ::: "memory")

#define MMA16816(d, a0,a1,a2,a3, b0,b1) \
    asm volatile( \
        "mma.sync.aligned.m16n8k16.row.col.f32.f16.f16.f32 " \
        "{%0,%1,%2,%3}, {%4,%5,%6,%7}, {%8,%9}, {%0,%1,%2,%3};\n" \
        : "+f"((d)[0]), "+f"((d)[1]), "+f"((d)[2]), "+f"((d)[3]) \
        : "r"(a0), "r"(a1), "r"(a2), "r"(a3), "r"(b0), "r"(b1))

// ---------------------------------------------------------------------------
// fp32 -> fp16 conversion (n % 8 == 0)
// ---------------------------------------------------------------------------
__global__ void f2h_kernel(const float4* __restrict__ s, uint4* __restrict__ d, int n8) {
    int i = blockIdx.x * blockDim.x + threadIdx.x;
    if (i < n8) {
        float4 a = s[2*i];
        float4 b = s[2*i + 1];
        d[i] = make_uint4(packh2(a.x, a.y), packh2(a.z, a.w),
                          packh2(b.x, b.y), packh2(b.z, b.w));
    }
}

// ---------------------------------------------------------------------------
// Meta + embedding
// ---------------------------------------------------------------------------
__global__ void meta_kernel(const int* __restrict__ ids, int* __restrict__ rel,
                            int* __restrict__ seg) {
    int b = blockIdx.x;
    if (threadIdx.x != 0) return;
    int last = 0, s = 0;
    for (int l = 0; l < LL; l++) {
        int id = ids[b*LL + l];
        if (id == EOS_ID) { last = l; s += 1; }
        rel[b*LL + l] = l - last;
        seg[b*LL + l] = s;
    }
}

__global__ __launch_bounds__(192)
void embed_kernel(const int* __restrict__ ids, const int* __restrict__ rel,
                  const float* __restrict__ tok, const float* __restrict__ pos,
                  float* __restrict__ x, __half* __restrict__ hx) {
    int row = blockIdx.x;
    int id = ids[row];
    int r  = rel[row];
    const float4* t = reinterpret_cast<const float4*>(tok + (size_t)id * DD);
    const float4* p = reinterpret_cast<const float4*>(pos + (size_t)r  * DD);
    float4* xo = reinterpret_cast<float4*>(x + (size_t)row*DD);
    uint2*  ho = reinterpret_cast<uint2*>(hx + (size_t)row*DD);
    const float sc = 27.712812921102035f;  // sqrt(768)
    int i = threadIdx.x;   // 0..191 (DD/4)
    float4 tv = t[i], pv = p[i];
    float4 v = make_float4(tv.x*sc + pv.x, tv.y*sc + pv.y,
                           tv.z*sc + pv.z, tv.w*sc + pv.w);
    xo[i] = v;
    ho[i] = make_uint2(packh2(v.x, v.y), packh2(v.z, v.w));
}

#define HSTR 40   // halves per smem row for GEMM (32 data + 8 pad)

// ---------------------------------------------------------------------------
// FP16-operand GEMM (R11/R14): C = A @ B^T (+bias)(+GELU). OUTH -> fp16 C.
// ---------------------------------------------------------------------------
template<bool GELU, bool OUTH>
__global__ __launch_bounds__(256, 2)
void gemm_h(const __half* __restrict__ A, const __half* __restrict__ B,
            const float* __restrict__ bias, void* __restrict__ Cv,
            int M, int N, int K) {
    __shared__ __align__(16) __half SA[2][128*HSTR];
    __shared__ __align__(16) __half SB[2][128*HSTR];

    const int bm = blockIdx.x * 128;
    const int bn = blockIdx.y * 128;
    const int tid  = threadIdx.x;
    const int warp = tid >> 5;
    const int lane = tid & 31;
    const int grp  = lane >> 2;
    const int qid  = lane & 3;

    const int wm = (warp >> 1) * 32;
    const int wn = (warp & 1) * 64;

    const int lrow  = lane & 15;
    const int lcol8 = (lane >> 4) << 3;
    uint32_t aoff[2], boff[4];
#pragma unroll
    for (int i = 0; i < 2; i++)
        aoff[i] = ((wm + i*16 + lrow) * HSTR + lcol8) * 2;
#pragma unroll
    for (int p = 0; p < 4; p++)
        boff[p] = ((wn + p*16 + lrow) * HSTR + lcol8) * 2;

    const uint32_t sa0 = smem_u32(&SA[0][0]), sa1 = smem_u32(&SA[1][0]);
    const uint32_t sb0 = smem_u32(&SB[0][0]), sb1 = smem_u32(&SB[1][0]);

    float acc[2][8][4];
#pragma unroll
    for (int i = 0; i < 2; i++)
#pragma unroll
        for (int j = 0; j < 8; j++)
#pragma unroll
            for (int c = 0; c < 4; c++) acc[i][j][c] = 0.f;

    const int ntiles = K >> 5;
    uint4 rA[2], rB[2];
    const uint4 zero4 = make_uint4(0u, 0u, 0u, 0u);

#pragma unroll
    for (int i = 0; i < 2; i++) {
        int idx = tid + (i << 8);
        int row = idx >> 2;
        int s8  = (idx & 3) << 3;
        rA[i] = *reinterpret_cast<const uint4*>(A + (size_t)(bm + row) * K + s8);
        int gn = bn + row;
        rB[i] = (gn < N) ? *reinterpret_cast<const uint4*>(B + (size_t)gn * K + s8)
                         : zero4;
    }
#pragma unroll
    for (int i = 0; i < 2; i++) {
        int idx = tid + (i << 8);
        int row = idx >> 2;
        int s8  = (idx & 3) << 3;
        *reinterpret_cast<uint4*>(&SA[0][row*HSTR + s8]) = rA[i];
        *reinterpret_cast<uint4*>(&SB[0][row*HSTR + s8]) = rB[i];
    }
    __syncthreads();

    for (int t = 0; t < ntiles; t++) {
        const int cb = t & 1;
        const bool more = (t + 1 < ntiles);

        if (more) {
            int kt = (t + 1) << 5;
#pragma unroll
            for (int i = 0; i < 2; i++) {
                int idx = tid + (i << 8);
                int row = idx >> 2;
                int s8  = (idx & 3) << 3;
                rA[i] = *reinterpret_cast<const uint4*>(A + (size_t)(bm + row) * K + kt + s8);
                int gn = bn + row;
                rB[i] = (gn < N) ? *reinterpret_cast<const uint4*>(B + (size_t)gn * K + kt + s8)
                                 : zero4;
            }
        }

        const uint32_t sa = cb ? sa1 : sa0;
        const uint32_t sb = cb ? sb1 : sb0;
#pragma unroll
        for (int ks = 0; ks < 2; ks++) {
            const uint32_t kb = ks * 32;
            uint32_t af[2][4];
#pragma unroll
            for (int i = 0; i < 2; i++)
                ldsm_x4(sa + aoff[i] + kb, af[i][0], af[i][1], af[i][2], af[i][3]);
#pragma unroll
            for (int p = 0; p < 4; p++) {
                uint32_t bf[4];
                ldsm_x4(sb + boff[p] + kb, bf[0], bf[1], bf[2], bf[3]);
#pragma unroll
                for (int i = 0; i < 2; i++) {
                    MMA16816(acc[i][2*p],   af[i][0], af[i][1], af[i][2], af[i][3], bf[0], bf[2]);
                    MMA16816(acc[i][2*p+1], af[i][0], af[i][1], af[i][2], af[i][3], bf[1], bf[3]);
                }
            }
        }

        if (more) {
            const int nb = (t + 1) & 1;
#pragma unroll
            for (int i = 0; i < 2; i++) {
                int idx = tid + (i << 8);
                int row = idx >> 2;
                int s8  = (idx & 3) << 3;
                *reinterpret_cast<uint4*>(&SA[nb][row*HSTR + s8]) = rA[i];
                *reinterpret_cast<uint4*>(&SB[nb][row*HSTR + s8]) = rB[i];
            }
        }
        __syncthreads();
    }

    float*  Cf = reinterpret_cast<float*>(Cv);
    __half* Ch = reinterpret_cast<__half*>(Cv);
    const bool evenN = (N & 1) == 0;
#pragma unroll
    for (int i = 0; i < 2; i++) {
#pragma unroll
        for (int j = 0; j < 8; j++) {
#pragma unroll
            for (int pr = 0; pr < 2; pr++) {
                int row = bm + wm + i*16 + grp + pr*8;
                int col = bn + wn + j*8 + (qid << 1);
                float v0 = acc[i][j][2*pr + 0];
                float v1 = acc[i][j][2*pr + 1];
                if (bias) { v0 += bias[col]; if (col + 1 < N) v1 += bias[col + 1]; }
                if (GELU) {
                    v0 = 0.5f * v0 * (1.0f + erff(v0 * 0.7071067811865475f));
                    v1 = 0.5f * v1 * (1.0f + erff(v1 * 0.7071067811865475f));
                }
                size_t base = (size_t)row * N + col;
                if (OUTH) {
                    if (col + 1 < N) {
                        *reinterpret_cast<uint32_t*>(&Ch[base]) = packh2(v0, v1);
                    } else if (col < N) {
                        Ch[base] = __float2half(v0);
                    }
                } else {
                    if (col + 1 < N) {
                        if (evenN) *reinterpret_cast<float2*>(&Cf[base]) = make_float2(v0, v1);
                        else { Cf[base] = v0; Cf[base + 1] = v1; }
                    } else if (col < N) {
                        Cf[base] = v0;
                    }
                }
            }
        }
    }
}

// ---------------------------------------------------------------------------
// Tensor-core flash attention with cp.async double-buffered K/V/seg.
// q-tile 128, kv-tile 64, 8 warps x 16 q-rows. fp16 qkv, fp32 softmax.
// Dynamic smem: Qh[128*ASTR] + {K,V}[2][64*ASTR] + seg[2][64].
// ---------------------------------------------------------------------------
#define ASTR 72
#define A_Q   0
#define A_K(buf)  (128*ASTR + (buf)*64*ASTR)
#define A_V(buf)  (128*ASTR + 2*64*ASTR + (buf)*64*ASTR)
#define A_SEG(buf) ((128*ASTR + 4*64*ASTR)*2 + (buf)*64*4)   // byte offset
#define ATT_SMEM ((128*ASTR + 4*64*ASTR)*2 + 2*64*4)

__global__ __launch_bounds__(256, 2)
void attn_mma_kernel(const __half* __restrict__ qkv, const int* __restrict__ seg,
                     __half* __restrict__ o) {
    extern __shared__ __align__(16) __half AS[];
    __half* Qh = AS;
    const uint32_t base  = smem_u32(AS);
    const uint32_t qbase = base;

    const int qt = blockIdx.x;
    const int h  = blockIdx.y;
    const int b  = blockIdx.z;
    const int tid  = threadIdx.x;
    const int warp = tid >> 5;
    const int lane = tid & 31;
    const int grp  = lane >> 2;
    const int qid  = lane & 3;
    const int q0 = qt * 128;

    const int lrow  = lane & 15;
    const int lcol8 = (lane >> 4) << 3;

    // issue K/V/seg loads for kv-tile kt into buffer buf
    auto issue = [&](int kt, int buf) {
        const int k0 = kt * 64;
#pragma unroll
        for (int i = 0; i < 2; i++) {
            int idx = tid + (i << 8);      // 0..511
            int r  = idx >> 3;             // 0..63
            int c8 = (idx & 7) << 3;
            const __half* src = qkv + (size_t)(b*LL + k0 + r)*(3*DD) + h*HD + c8;
            cpa16(base + (A_K(buf) + r*ASTR + c8)*2, src + DD);
            cpa16(base + (A_V(buf) + r*ASTR + c8)*2, src + 2*DD);
        }
        if (tid < 16)
            cpa16(base + A_SEG(buf) + tid*16, seg + b*LL + k0 + tid*4);
    };

    // load Q (scaled by exact 0.125 in fp16) -> smem (regular stores)
    const __half2 sc2 = __floats2half2_rn(0.125f, 0.125f);
#pragma unroll
    for (int i = 0; i < 4; i++) {
        int idx = tid + (i << 8);
        int r  = idx >> 3;
        int c8 = (idx & 7) << 3;
        uint4 v = *reinterpret_cast<const uint4*>(
            qkv + (size_t)(b*LL + q0 + r)*(3*DD) + h*HD + c8);
        __half2* hv = reinterpret_cast<__half2*>(&v);
#pragma unroll
        for (int c = 0; c < 4; c++) hv[c] = __hmul2(hv[c], sc2);
        *reinterpret_cast<uint4*>(&Qh[r*ASTR + c8]) = v;
    }

    const int qg0 = q0 + warp*16 + grp;
    const int qg1 = qg0 + 8;
    const int qseg0 = seg[b*LL + qg0];
    const int qseg1 = seg[b*LL + qg1];

    float m0 = -1e30f, m1 = -1e30f, l0 = 0.f, l1 = 0.f;
    float O[8][4];
#pragma unroll
    for (int j = 0; j < 8; j++)
#pragma unroll
        for (int c = 0; c < 4; c++) O[j][c] = 0.f;

    const int ntiles = 2*qt + 2;
    issue(0, 0);
    CP_COMMIT();

    for (int kt = 0; kt < ntiles; kt++) {
        const int cb = kt & 1;
        const int k0 = kt * 64;
        const bool more = (kt + 1 < ntiles);

        if (more) { issue(kt + 1, cb ^ 1); CP_COMMIT(); }
        if (more) CP_WAIT1(); else CP_WAIT0();
        __syncthreads();

        const uint32_t kbase = base + A_K(cb)*2;
        const uint32_t vbase = base + A_V(cb)*2;
        const int* sseg = reinterpret_cast<const int*>(
            reinterpret_cast<const char*>(AS) + A_SEG(cb));

        float s[8][4];
#pragma unroll
        for (int j = 0; j < 8; j++)
#pragma unroll
            for (int c = 0; c < 4; c++) s[j][c] = 0.f;
#pragma unroll
        for (int ks = 0; ks < 4; ks++) {
            uint32_t aq[4];
            ldsm_x4(qbase + ((warp*16 + lrow)*ASTR + ks*16 + lcol8)*2,
                    aq[0], aq[1], aq[2], aq[3]);
#pragma unroll
            for (int p = 0; p < 4; p++) {
                uint32_t bf[4];
                ldsm_x4(kbase + ((p*16 + lrow)*ASTR + ks*16 + lcol8)*2,
                        bf[0], bf[1], bf[2], bf[3]);
                MMA16816(s[2*p],   aq[0], aq[1], aq[2], aq[3], bf[0], bf[2]);
                MMA16816(s[2*p+1], aq[0], aq[1], aq[2], aq[3], bf[1], bf[3]);
            }
        }

        float mt0 = -1e30f, mt1 = -1e30f;
#pragma unroll
        for (int j = 0; j < 8; j++) {
            int kg0 = k0 + 8*j + 2*qid;
            int sg0 = sseg[8*j + 2*qid];
            int sg1 = sseg[8*j + 2*qid + 1];
            s[j][0] = (kg0     <= qg0 && sg0 == qseg0) ? s[j][0] : -1e30f;
            s[j][1] = (kg0 + 1 <= qg0 && sg1 == qseg0) ? s[j][1] : -1e30f;
            s[j][2] = (kg0     <= qg1 && sg0 == qseg1) ? s[j][2] : -1e30f;
            s[j][3] = (kg0 + 1 <= qg1 && sg1 == qseg1) ? s[j][3] : -1e30f;
            mt0 = fmaxf(mt0, fmaxf(s[j][0], s[j][1]));
            mt1 = fmaxf(mt1, fmaxf(s[j][2], s[j][3]));
        }
#pragma unroll
        for (int off = 1; off < 4; off <<= 1) {
            mt0 = fmaxf(mt0, __shfl_xor_sync(0xffffffffu, mt0, off));
            mt1 = fmaxf(mt1, __shfl_xor_sync(0xffffffffu, mt1, off));
        }
        float mn0 = fmaxf(m0, mt0), mn1 = fmaxf(m1, mt1);
        float f0 = __expf(m0 - mn0), f1 = __expf(m1 - mn1);
        m0 = mn0; m1 = mn1;
        float rs0 = 0.f, rs1 = 0.f;
#pragma unroll
        for (int j = 0; j < 8; j++) {
            s[j][0] = __expf(s[j][0] - mn0);
            s[j][1] = __expf(s[j][1] - mn0);
            s[j][2] = __expf(s[j][2] - mn1);
            s[j][3] = __expf(s[j][3] - mn1);
            rs0 += s[j][0] + s[j][1];
            rs1 += s[j][2] + s[j][3];
            O[j][0] *= f0; O[j][1] *= f0;
            O[j][2] *= f1; O[j][3] *= f1;
        }
#pragma unroll
        for (int off = 1; off < 4; off <<= 1) {
            rs0 += __shfl_xor_sync(0xffffffffu, rs0, off);
            rs1 += __shfl_xor_sync(0xffffffffu, rs1, off);
        }
        l0 = l0 * f0 + rs0;
        l1 = l1 * f1 + rs1;

        uint32_t ap[4][4];
#pragma unroll
        for (int ks = 0; ks < 4; ks++) {
            ap[ks][0] = packh2(s[2*ks][0],   s[2*ks][1]);
            ap[ks][1] = packh2(s[2*ks][2],   s[2*ks][3]);
            ap[ks][2] = packh2(s[2*ks+1][0], s[2*ks+1][1]);
            ap[ks][3] = packh2(s[2*ks+1][2], s[2*ks+1][3]);
        }

#pragma unroll
        for (int ks = 0; ks < 4; ks++) {
#pragma unroll
            for (int p = 0; p < 4; p++) {
                uint32_t bv[4];
                ldsm_x4_t(vbase + ((ks*16 + lrow)*ASTR + p*16 + lcol8)*2,
                          bv[0], bv[1], bv[2], bv[3]);
                MMA16816(O[2*p],   ap[ks][0], ap[ks][1], ap[ks][2], ap[ks][3], bv[0], bv[1]);
                MMA16816(O[2*p+1], ap[ks][0], ap[ks][1], ap[ks][2], ap[ks][3], bv[2], bv[3]);
            }
        }
        __syncthreads();   // all warps done reading cb before it is re-issued
    }

    float inv0 = 1.0f / l0, inv1 = 1.0f / l1;
#pragma unroll
    for (int j = 0; j < 8; j++) {
        int col = h*HD + 8*j + 2*qid;
        *reinterpret_cast<uint32_t*>(&o[(size_t)(b*LL + qg0)*DD + col]) =
            packh2(O[j][0]*inv0, O[j][1]*inv0);
        *reinterpret_cast<uint32_t*>(&o[(size_t)(b*LL + qg1)*DD + col]) =
            packh2(O[j][2]*inv1, O[j][3]*inv1);
    }
}

// ---------------------------------------------------------------------------
// add+LN, warp-per-row (R14)
// ---------------------------------------------------------------------------
__global__ __launch_bounds__(256)
void add_ln_kernel(float* __restrict__ x, const float* __restrict__ r,
                   const float* __restrict__ w, const float* __restrict__ b,
                   __half* __restrict__ hx) {
    const int wid  = threadIdx.x >> 5;
    const int lane = threadIdx.x & 31;
    const int row  = blockIdx.x * 8 + wid;

    const float4* xr = reinterpret_cast<const float4*>(x + (size_t)row*DD);
    const float4* rr = reinterpret_cast<const float4*>(r + (size_t)row*DD);
    const float4* wr = reinterpret_cast<const float4*>(w);
    const float4* br = reinterpret_cast<const float4*>(b);

    float4 v[6];
    float s = 0.f;
#pragma unroll
    for (int j = 0; j < 6; j++) {
        float4 a = xr[lane + 32*j];
        float4 c = rr[lane + 32*j];
        a.x += c.x; a.y += c.y; a.z += c.z; a.w += c.w;
        v[j] = a;
        s += a.x + a.y + a.z + a.w;
    }
#pragma unroll
    for (int off = 16; off; off >>= 1) s += __shfl_xor_sync(0xffffffffu, s, off);
    const float mean = s * (1.0f / DD);

    float vs = 0.f;
#pragma unroll
    for (int j = 0; j < 6; j++) {
        float dx = v[j].x - mean, dy = v[j].y - mean;
        float dz = v[j].z - mean, dw = v[j].w - mean;
        vs += dx*dx + dy*dy + dz*dz + dw*dw;
    }
#pragma unroll
    for (int off = 16; off; off >>= 1) vs += __shfl_xor_sync(0xffffffffu, vs, off);
    const float inv = rsqrtf(vs * (1.0f / DD) + 1e-5f);

    float4* xo = reinterpret_cast<float4*>(x + (size_t)row*DD);
    uint2*  ho = reinterpret_cast<uint2*>(hx + (size_t)row*DD);
#pragma unroll
    for (int j = 0; j < 6; j++) {
        float4 ww = wr[lane + 32*j];
        float4 bb = br[lane + 32*j];
        float4 o;
        o.x = (v[j].x - mean) * inv * ww.x + bb.x;
        o.y = (v[j].y - mean) * inv * ww.y + bb.y;
        o.z = (v[j].z - mean) * inv * ww.z + bb.z;
        o.w = (v[j].w - mean) * inv * ww.w + bb.w;
        xo[lane + 32*j] = o;
        ho[lane + 32*j] = make_uint2(packh2(o.x, o.y), packh2(o.z, o.w));
    }
}

// ---------------------------------------------------------------------------
// Host launcher
// ---------------------------------------------------------------------------
static inline void conv(const float* s, __half* d, long n) {
    int n8 = (int)(n / 8);
    int blocks = (n8 + 255) / 256;
    f2h_kernel<<<blocks, 256>>>((const float4*)s, (uint4*)d, n8);
}

extern "C" void kernel_launch(void* const* d_in, const int* in_sizes, int n_in,
                              void* d_out, int out_size) {
    const int*   ids   = (const int*)  d_in[0];
    const float* tok   = (const float*)d_in[1];
    const float* pos   = (const float*)d_in[2];
    const float* qkv_w = (const float*)d_in[3];
    const float* qkv_b = (const float*)d_in[4];
    const float* out_w = (const float*)d_in[5];
    const float* out_b = (const float*)d_in[6];
    const float* ln1_w = (const float*)d_in[7];
    const float* ln1_b = (const float*)d_in[8];
    const float* ln2_w = (const float*)d_in[9];
    const float* ln2_b = (const float*)d_in[10];
    const float* ff1_w = (const float*)d_in[11];
    const float* ff1_b = (const float*)d_in[12];
    const float* ff2_w = (const float*)d_in[13];
    const float* ff2_b = (const float*)d_in[14];
    float* out = (float*)d_out;

    float *x, *tmp;
    int *rel, *seg;
    __half *hqkv, *hx, *hatt, *hff, *htok, *hqkvw, *houtw, *hff1w, *hff2w;
    cudaGetSymbolAddress((void**)&x,    g_x);
    cudaGetSymbolAddress((void**)&tmp,  g_tmp);
    cudaGetSymbolAddress((void**)&rel,  g_rel);
    cudaGetSymbolAddress((void**)&seg,  g_seg);
    cudaGetSymbolAddress((void**)&hqkv, h_qkv);
    cudaGetSymbolAddress((void**)&hx,   h_x);
    cudaGetSymbolAddress((void**)&hatt, h_att);
    cudaGetSymbolAddress((void**)&hff,  h_ff);
    cudaGetSymbolAddress((void**)&htok, h_tok);
    cudaGetSymbolAddress((void**)&hqkvw, h_qkvw);
    cudaGetSymbolAddress((void**)&houtw, h_outw);
    cudaGetSymbolAddress((void**)&hff1w, h_ff1w);
    cudaGetSymbolAddress((void**)&hff2w, h_ff2w);

    cudaFuncSetAttribute(attn_mma_kernel,
        cudaFuncAttributeMaxDynamicSharedMemorySize, ATT_SMEM);

    // operand conversions (deterministic, every launch)
    conv(tok,   htok,  (long)VV*DD);
    conv(qkv_w, hqkvw, (long)NLAY*3*DD*DD);
    conv(out_w, houtw, (long)NLAY*DD*DD);
    conv(ff1_w, hff1w, (long)NLAY*DFFN*DD);
    conv(ff2_w, hff2w, (long)NLAY*DD*DFFN);

    meta_kernel<<<BB, 32>>>(ids, rel, seg);
    embed_kernel<<<ROWS, 192>>>(ids, rel, tok, pos, x, hx);

    const int MT = ROWS / 128;  // 16, fast axis

    for (int l = 0; l < NLAY; l++) {
        gemm_h<false,true><<<dim3(MT, 3*DD/128), 256>>>(
            hx, hqkvw + (size_t)l*3*DD*DD, qkv_b + (size_t)l*3*DD, hqkv,
            ROWS, 3*DD, DD);

        attn_mma_kernel<<<dim3(LL/128, HH, BB), 256, ATT_SMEM>>>(hqkv, seg, hatt);

        gemm_h<false,false><<<dim3(MT, DD/128), 256>>>(
            hatt, houtw + (size_t)l*DD*DD, out_b + (size_t)l*DD, tmp,
            ROWS, DD, DD);

        add_ln_kernel<<<ROWS/8, 256>>>(x, tmp, ln1_w + (size_t)l*DD, ln1_b + (size_t)l*DD, hx);

        gemm_h<true,true><<<dim3(MT, DFFN/128), 256>>>(
            hx, hff1w + (size_t)l*DFFN*DD, ff1_b + (size_t)l*DFFN, hff,
            ROWS, DFFN, DD);

        gemm_h<false,false><<<dim3(MT, DD/128), 256>>>(
            hff, hff2w + (size_t)l*DD*DFFN, ff2_b + (size_t)l*DD, tmp,
            ROWS, DD, DFFN);

        add_ln_kernel<<<ROWS/8, 256>>>(x, tmp, ln2_w + (size_t)l*DD, ln2_b + (size_t)l*DD, hx);
    }

    gemm_h<false,false><<<dim3(MT, (VV + 127)/128), 256>>>(
        hx, htok, nullptr, out, ROWS, VV, DD);
}

// round 16
// speedup vs baseline: 1.0672x; 1.0143x over previous
#include <cuda_runtime.h>
#include <cuda_fp16.h>
#include <math.h>
#include <stdint.h>

// Problem constants
#define BB   2
#define LL   1024
#define DD   768
#define HH   12
#define HD   64
#define NLAY 2
#define DFFN 3072
#define VV   50257
#define EOS_ID 50256
#define ROWS (BB*LL)          // 2048

// ---------------------------------------------------------------------------
// Static scratch
// ---------------------------------------------------------------------------
__device__ float  g_x[ROWS*DD];
__device__ float  g_tmp[ROWS*DD];
__device__ int    g_rel[ROWS];
__device__ int    g_seg[ROWS];
// fp16 tensors
__device__ __half h_qkv[ROWS*3*DD];
__device__ __half h_x[ROWS*DD];
__device__ __half h_att[ROWS*DD];
__device__ __half h_ff[ROWS*DFFN];
__device__ __half h_tok[VV*DD];
__device__ __half h_qkvw[NLAY*3*DD*DD];
__device__ __half h_outw[NLAY*DD*DD];
__device__ __half h_ff1w[NLAY*DFFN*DD];
__device__ __half h_ff2w[NLAY*DD*DFFN];

__device__ __forceinline__ uint32_t smem_u32(const void* p) {
    uint32_t a;
    asm("{ .reg .u64 t; cvta.to.shared.u64 t, %1; cvt.u32.u64 %0, t; }"
        : "=r"(a) : "l"(p));
    return a;
}

__device__ __forceinline__ uint32_t packh2(float x, float y) {
    __half2 h = __floats2half2_rn(x, y);
    return *reinterpret_cast<uint32_t*>(&h);
}

__device__ __forceinline__ void ldsm_x4(uint32_t addr, uint32_t& r0, uint32_t& r1,
                                        uint32_t& r2, uint32_t& r3) {
    asm volatile("ldmatrix.sync.aligned.m8n8.x4.shared.b16 {%0,%1,%2,%3}, [%4];"
                 : "=r"(r0), "=r"(r1), "=r"(r2), "=r"(r3) : "r"(addr));
}

__device__ __forceinline__ void ldsm_x4_t(uint32_t addr, uint32_t& r0, uint32_t& r1,
                                          uint32_t& r2, uint32_t& r3) {
    asm volatile("ldmatrix.sync.aligned.m8n8.x4.trans.shared.b16 {%0,%1,%2,%3}, [%4];"
                 : "=r"(r0), "=r"(r1), "=r"(r2), "=r"(r3) : "r"(addr));
}

__device__ __forceinline__ void cpa16(uint32_t dst, const void* src) {
    asm volatile("cp.async.cg.shared.global [%0], [%1], 16;"
                 :: "r"(dst), "l"(src));
}
#define CP_COMMIT() asm volatile("cp.async.commit_group;" ::: "memory")
#define CP_WAIT0()  asm volatile("cp.async.wait_group 0;" ::: "memory")
#define CP_WAIT1()  asm volatile("cp.async.wait_group 1;" ::: "memory")

#define MMA16816(d, a0,a1,a2,a3, b0,b1) \
    asm volatile( \
        "mma.sync.aligned.m16n8k16.row.col.f32.f16.f16.f32 " \
        "{%0,%1,%2,%3}, {%4,%5,%6,%7}, {%8,%9}, {%0,%1,%2,%3};\n" \
        : "+f"((d)[0]), "+f"((d)[1]), "+f"((d)[2]), "+f"((d)[3]) \
        : "r"(a0), "r"(a1), "r"(a2), "r"(a3), "r"(b0), "r"(b1))

// ---------------------------------------------------------------------------
// fp32 -> fp16 conversion (n % 8 == 0)
// ---------------------------------------------------------------------------
__global__ void f2h_kernel(const float4* __restrict__ s, uint4* __restrict__ d, int n8) {
    int i = blockIdx.x * blockDim.x + threadIdx.x;
    if (i < n8) {
        float4 a = s[2*i];
        float4 b = s[2*i + 1];
        d[i] = make_uint4(packh2(a.x, a.y), packh2(a.z, a.w),
                          packh2(b.x, b.y), packh2(b.z, b.w));
    }
}

// ---------------------------------------------------------------------------
// Meta + embedding
// ---------------------------------------------------------------------------
__global__ void meta_kernel(const int* __restrict__ ids, int* __restrict__ rel,
                            int* __restrict__ seg) {
    int b = blockIdx.x;
    if (threadIdx.x != 0) return;
    int last = 0, s = 0;
    for (int l = 0; l < LL; l++) {
        int id = ids[b*LL + l];
        if (id == EOS_ID) { last = l; s += 1; }
        rel[b*LL + l] = l - last;
        seg[b*LL + l] = s;
    }
}

__global__ __launch_bounds__(192)
void embed_kernel(const int* __restrict__ ids, const int* __restrict__ rel,
                  const float* __restrict__ tok, const float* __restrict__ pos,
                  float* __restrict__ x, __half* __restrict__ hx) {
    int row = blockIdx.x;
    int id = ids[row];
    int r  = rel[row];
    const float4* t = reinterpret_cast<const float4*>(tok + (size_t)id * DD);
    const float4* p = reinterpret_cast<const float4*>(pos + (size_t)r  * DD);
    float4* xo = reinterpret_cast<float4*>(x + (size_t)row*DD);
    uint2*  ho = reinterpret_cast<uint2*>(hx + (size_t)row*DD);
    const float sc = 27.712812921102035f;  // sqrt(768)
    int i = threadIdx.x;
    float4 tv = t[i], pv = p[i];
    float4 v = make_float4(tv.x*sc + pv.x, tv.y*sc + pv.y,
                           tv.z*sc + pv.z, tv.w*sc + pv.w);
    xo[i] = v;
    ho[i] = make_uint2(packh2(v.x, v.y), packh2(v.z, v.w));
}

#define HSTR 40   // halves per smem row for GEMM (32 data + 8 pad)

// ---------------------------------------------------------------------------
// FP16-operand GEMM, BM=128 (R11/R14): C = A @ B^T (+bias)(+GELU).
// ---------------------------------------------------------------------------
template<bool GELU, bool OUTH>
__global__ __launch_bounds__(256, 2)
void gemm_h(const __half* __restrict__ A, const __half* __restrict__ B,
            const float* __restrict__ bias, void* __restrict__ Cv,
            int M, int N, int K) {
    __shared__ __align__(16) __half SA[2][128*HSTR];
    __shared__ __align__(16) __half SB[2][128*HSTR];

    const int bm = blockIdx.x * 128;
    const int bn = blockIdx.y * 128;
    const int tid  = threadIdx.x;
    const int warp = tid >> 5;
    const int lane = tid & 31;
    const int grp  = lane >> 2;
    const int qid  = lane & 3;

    const int wm = (warp >> 1) * 32;
    const int wn = (warp & 1) * 64;

    const int lrow  = lane & 15;
    const int lcol8 = (lane >> 4) << 3;
    uint32_t aoff[2], boff[4];
#pragma unroll
    for (int i = 0; i < 2; i++)
        aoff[i] = ((wm + i*16 + lrow) * HSTR + lcol8) * 2;
#pragma unroll
    for (int p = 0; p < 4; p++)
        boff[p] = ((wn + p*16 + lrow) * HSTR + lcol8) * 2;

    const uint32_t sa0 = smem_u32(&SA[0][0]), sa1 = smem_u32(&SA[1][0]);
    const uint32_t sb0 = smem_u32(&SB[0][0]), sb1 = smem_u32(&SB[1][0]);

    float acc[2][8][4];
#pragma unroll
    for (int i = 0; i < 2; i++)
#pragma unroll
        for (int j = 0; j < 8; j++)
#pragma unroll
            for (int c = 0; c < 4; c++) acc[i][j][c] = 0.f;

    const int ntiles = K >> 5;
    uint4 rA[2], rB[2];
    const uint4 zero4 = make_uint4(0u, 0u, 0u, 0u);

#pragma unroll
    for (int i = 0; i < 2; i++) {
        int idx = tid + (i << 8);
        int row = idx >> 2;
        int s8  = (idx & 3) << 3;
        rA[i] = *reinterpret_cast<const uint4*>(A + (size_t)(bm + row) * K + s8);
        int gn = bn + row;
        rB[i] = (gn < N) ? *reinterpret_cast<const uint4*>(B + (size_t)gn * K + s8)
                         : zero4;
    }
#pragma unroll
    for (int i = 0; i < 2; i++) {
        int idx = tid + (i << 8);
        int row = idx >> 2;
        int s8  = (idx & 3) << 3;
        *reinterpret_cast<uint4*>(&SA[0][row*HSTR + s8]) = rA[i];
        *reinterpret_cast<uint4*>(&SB[0][row*HSTR + s8]) = rB[i];
    }
    __syncthreads();

    for (int t = 0; t < ntiles; t++) {
        const int cb = t & 1;
        const bool more = (t + 1 < ntiles);

        if (more) {
            int kt = (t + 1) << 5;
#pragma unroll
            for (int i = 0; i < 2; i++) {
                int idx = tid + (i << 8);
                int row = idx >> 2;
                int s8  = (idx & 3) << 3;
                rA[i] = *reinterpret_cast<const uint4*>(A + (size_t)(bm + row) * K + kt + s8);
                int gn = bn + row;
                rB[i] = (gn < N) ? *reinterpret_cast<const uint4*>(B + (size_t)gn * K + kt + s8)
                                 : zero4;
            }
        }

        const uint32_t sa = cb ? sa1 : sa0;
        const uint32_t sb = cb ? sb1 : sb0;
#pragma unroll
        for (int ks = 0; ks < 2; ks++) {
            const uint32_t kb = ks * 32;
            uint32_t af[2][4];
#pragma unroll
            for (int i = 0; i < 2; i++)
                ldsm_x4(sa + aoff[i] + kb, af[i][0], af[i][1], af[i][2], af[i][3]);
#pragma unroll
            for (int p = 0; p < 4; p++) {
                uint32_t bf[4];
                ldsm_x4(sb + boff[p] + kb, bf[0], bf[1], bf[2], bf[3]);
#pragma unroll
                for (int i = 0; i < 2; i++) {
                    MMA16816(acc[i][2*p],   af[i][0], af[i][1], af[i][2], af[i][3], bf[0], bf[2]);
                    MMA16816(acc[i][2*p+1], af[i][0], af[i][1], af[i][2], af[i][3], bf[1], bf[3]);
                }
            }
        }

        if (more) {
            const int nb = (t + 1) & 1;
#pragma unroll
            for (int i = 0; i < 2; i++) {
                int idx = tid + (i << 8);
                int row = idx >> 2;
                int s8  = (idx & 3) << 3;
                *reinterpret_cast<uint4*>(&SA[nb][row*HSTR + s8]) = rA[i];
                *reinterpret_cast<uint4*>(&SB[nb][row*HSTR + s8]) = rB[i];
            }
        }
        __syncthreads();
    }

    float*  Cf = reinterpret_cast<float*>(Cv);
    __half* Ch = reinterpret_cast<__half*>(Cv);
    const bool evenN = (N & 1) == 0;
#pragma unroll
    for (int i = 0; i < 2; i++) {
#pragma unroll
        for (int j = 0; j < 8; j++) {
#pragma unroll
            for (int pr = 0; pr < 2; pr++) {
                int row = bm + wm + i*16 + grp + pr*8;
                int col = bn + wn + j*8 + (qid << 1);
                float v0 = acc[i][j][2*pr + 0];
                float v1 = acc[i][j][2*pr + 1];
                if (bias) { v0 += bias[col]; if (col + 1 < N) v1 += bias[col + 1]; }
                if (GELU) {
                    v0 = 0.5f * v0 * (1.0f + erff(v0 * 0.7071067811865475f));
                    v1 = 0.5f * v1 * (1.0f + erff(v1 * 0.7071067811865475f));
                }
                size_t base = (size_t)row * N + col;
                if (OUTH) {
                    if (col + 1 < N) {
                        *reinterpret_cast<uint32_t*>(&Ch[base]) = packh2(v0, v1);
                    } else if (col < N) {
                        Ch[base] = __float2half(v0);
                    }
                } else {
                    if (col + 1 < N) {
                        if (evenN) *reinterpret_cast<float2*>(&Cf[base]) = make_float2(v0, v1);
                        else { Cf[base] = v0; Cf[base + 1] = v1; }
                    } else if (col < N) {
                        Cf[base] = v0;
                    }
                }
            }
        }
    }
}

// ---------------------------------------------------------------------------
// FP16 GEMM, BM=64 (for small-grid N=768 GEMMs): C_fp32 = A @ B^T + bias.
// 64x128 tile, 8 warps as 2m x 4n, warp tile 32x32. N even, no guard needed
// for our uses (N=768), but keep the guard for safety.
// ---------------------------------------------------------------------------
__global__ __launch_bounds__(256, 2)
void gemm_h64(const __half* __restrict__ A, const __half* __restrict__ B,
              const float* __restrict__ bias, float* __restrict__ C,
              int M, int N, int K) {
    __shared__ __align__(16) __half SA[2][64*HSTR];
    __shared__ __align__(16) __half SB[2][128*HSTR];

    const int bm = blockIdx.x * 64;
    const int bn = blockIdx.y * 128;
    const int tid  = threadIdx.x;
    const int warp = tid >> 5;
    const int lane = tid & 31;
    const int grp  = lane >> 2;
    const int qid  = lane & 3;

    const int wm = (warp >> 2) * 32;   // 2 m-groups
    const int wn = (warp & 3) * 32;    // 4 n-groups

    const int lrow  = lane & 15;
    const int lcol8 = (lane >> 4) << 3;
    uint32_t aoff[2], boff[2];
#pragma unroll
    for (int i = 0; i < 2; i++)
        aoff[i] = ((wm + i*16 + lrow) * HSTR + lcol8) * 2;
#pragma unroll
    for (int p = 0; p < 2; p++)
        boff[p] = ((wn + p*16 + lrow) * HSTR + lcol8) * 2;

    const uint32_t sa0 = smem_u32(&SA[0][0]), sa1 = smem_u32(&SA[1][0]);
    const uint32_t sb0 = smem_u32(&SB[0][0]), sb1 = smem_u32(&SB[1][0]);

    float acc[2][4][4];
#pragma unroll
    for (int i = 0; i < 2; i++)
#pragma unroll
        for (int j = 0; j < 4; j++)
#pragma unroll
            for (int c = 0; c < 4; c++) acc[i][j][c] = 0.f;

    const int ntiles = K >> 5;
    uint4 rA, rB[2];
    const uint4 zero4 = make_uint4(0u, 0u, 0u, 0u);

    // A: 64 rows x 4 chunks = 256 chunks (1/thread); B: 512 chunks (2/thread)
    const int a_row = tid >> 2, a_c8 = (tid & 3) << 3;
    {
        rA = *reinterpret_cast<const uint4*>(A + (size_t)(bm + a_row) * K + a_c8);
#pragma unroll
        for (int i = 0; i < 2; i++) {
            int idx = tid + (i << 8);
            int row = idx >> 2;
            int s8  = (idx & 3) << 3;
            int gn = bn + row;
            rB[i] = (gn < N) ? *reinterpret_cast<const uint4*>(B + (size_t)gn * K + s8)
                             : zero4;
        }
        *reinterpret_cast<uint4*>(&SA[0][a_row*HSTR + a_c8]) = rA;
#pragma unroll
        for (int i = 0; i < 2; i++) {
            int idx = tid + (i << 8);
            int row = idx >> 2;
            int s8  = (idx & 3) << 3;
            *reinterpret_cast<uint4*>(&SB[0][row*HSTR + s8]) = rB[i];
        }
    }
    __syncthreads();

    for (int t = 0; t < ntiles; t++) {
        const int cb = t & 1;
        const bool more = (t + 1 < ntiles);

        if (more) {
            int kt = (t + 1) << 5;
            rA = *reinterpret_cast<const uint4*>(A + (size_t)(bm + a_row) * K + kt + a_c8);
#pragma unroll
            for (int i = 0; i < 2; i++) {
                int idx = tid + (i << 8);
                int row = idx >> 2;
                int s8  = (idx & 3) << 3;
                int gn = bn + row;
                rB[i] = (gn < N) ? *reinterpret_cast<const uint4*>(B + (size_t)gn * K + kt + s8)
                                 : zero4;
            }
        }

        const uint32_t sa = cb ? sa1 : sa0;
        const uint32_t sb = cb ? sb1 : sb0;
#pragma unroll
        for (int ks = 0; ks < 2; ks++) {
            const uint32_t kb = ks * 32;
            uint32_t af[2][4];
#pragma unroll
            for (int i = 0; i < 2; i++)
                ldsm_x4(sa + aoff[i] + kb, af[i][0], af[i][1], af[i][2], af[i][3]);
#pragma unroll
            for (int p = 0; p < 2; p++) {
                uint32_t bf[4];
                ldsm_x4(sb + boff[p] + kb, bf[0], bf[1], bf[2], bf[3]);
#pragma unroll
                for (int i = 0; i < 2; i++) {
                    MMA16816(acc[i][2*p],   af[i][0], af[i][1], af[i][2], af[i][3], bf[0], bf[2]);
                    MMA16816(acc[i][2*p+1], af[i][0], af[i][1], af[i][2], af[i][3], bf[1], bf[3]);
                }
            }
        }

        if (more) {
            const int nb = (t + 1) & 1;
            *reinterpret_cast<uint4*>(&SA[nb][a_row*HSTR + a_c8]) = rA;
#pragma unroll
            for (int i = 0; i < 2; i++) {
                int idx = tid + (i << 8);
                int row = idx >> 2;
                int s8  = (idx & 3) << 3;
                *reinterpret_cast<uint4*>(&SB[nb][row*HSTR + s8]) = rB[i];
            }
        }
        __syncthreads();
    }

#pragma unroll
    for (int i = 0; i < 2; i++) {
#pragma unroll
        for (int j = 0; j < 4; j++) {
#pragma unroll
            for (int pr = 0; pr < 2; pr++) {
                int row = bm + wm + i*16 + grp + pr*8;
                int col = bn + wn + j*8 + (qid << 1);
                if (col + 1 < N) {
                    float v0 = acc[i][j][2*pr + 0] + (bias ? bias[col] : 0.f);
                    float v1 = acc[i][j][2*pr + 1] + (bias ? bias[col + 1] : 0.f);
                    *reinterpret_cast<float2*>(&C[(size_t)row * N + col]) =
                        make_float2(v0, v1);
                }
            }
        }
    }
}

// ---------------------------------------------------------------------------
// Tensor-core flash attention with cp.async double-buffered K/V/seg (R15).
// ---------------------------------------------------------------------------
#define ASTR 72
#define A_K(buf)  (128*ASTR + (buf)*64*ASTR)
#define A_V(buf)  (128*ASTR + 2*64*ASTR + (buf)*64*ASTR)
#define A_SEG(buf) ((128*ASTR + 4*64*ASTR)*2 + (buf)*64*4)
#define ATT_SMEM ((128*ASTR + 4*64*ASTR)*2 + 2*64*4)

__global__ __launch_bounds__(256, 2)
void attn_mma_kernel(const __half* __restrict__ qkv, const int* __restrict__ seg,
                     __half* __restrict__ o) {
    extern __shared__ __align__(16) __half AS[];
    __half* Qh = AS;
    const uint32_t base  = smem_u32(AS);
    const uint32_t qbase = base;

    const int qt = blockIdx.x;
    const int h  = blockIdx.y;
    const int b  = blockIdx.z;
    const int tid  = threadIdx.x;
    const int warp = tid >> 5;
    const int lane = tid & 31;
    const int grp  = lane >> 2;
    const int qid  = lane & 3;
    const int q0 = qt * 128;

    const int lrow  = lane & 15;
    const int lcol8 = (lane >> 4) << 3;

    auto issue = [&](int kt, int buf) {
        const int k0 = kt * 64;
#pragma unroll
        for (int i = 0; i < 2; i++) {
            int idx = tid + (i << 8);
            int r  = idx >> 3;
            int c8 = (idx & 7) << 3;
            const __half* src = qkv + (size_t)(b*LL + k0 + r)*(3*DD) + h*HD + c8;
            cpa16(base + (A_K(buf) + r*ASTR + c8)*2, src + DD);
            cpa16(base + (A_V(buf) + r*ASTR + c8)*2, src + 2*DD);
        }
        if (tid < 16)
            cpa16(base + A_SEG(buf) + tid*16, seg + b*LL + k0 + tid*4);
    };

    const __half2 sc2 = __floats2half2_rn(0.125f, 0.125f);
#pragma unroll
    for (int i = 0; i < 4; i++) {
        int idx = tid + (i << 8);
        int r  = idx >> 3;
        int c8 = (idx & 7) << 3;
        uint4 v = *reinterpret_cast<const uint4*>(
            qkv + (size_t)(b*LL + q0 + r)*(3*DD) + h*HD + c8);
        __half2* hv = reinterpret_cast<__half2*>(&v);
#pragma unroll
        for (int c = 0; c < 4; c++) hv[c] = __hmul2(hv[c], sc2);
        *reinterpret_cast<uint4*>(&Qh[r*ASTR + c8]) = v;
    }

    const int qg0 = q0 + warp*16 + grp;
    const int qg1 = qg0 + 8;
    const int qseg0 = seg[b*LL + qg0];
    const int qseg1 = seg[b*LL + qg1];

    float m0 = -1e30f, m1 = -1e30f, l0 = 0.f, l1 = 0.f;
    float O[8][4];
#pragma unroll
    for (int j = 0; j < 8; j++)
#pragma unroll
        for (int c = 0; c < 4; c++) O[j][c] = 0.f;

    const int ntiles = 2*qt + 2;
    issue(0, 0);
    CP_COMMIT();

    for (int kt = 0; kt < ntiles; kt++) {
        const int cb = kt & 1;
        const int k0 = kt * 64;
        const bool more = (kt + 1 < ntiles);

        if (more) { issue(kt + 1, cb ^ 1); CP_COMMIT(); }
        if (more) CP_WAIT1(); else CP_WAIT0();
        __syncthreads();

        const uint32_t kbase = base + A_K(cb)*2;
        const uint32_t vbase = base + A_V(cb)*2;
        const int* sseg = reinterpret_cast<const int*>(
            reinterpret_cast<const char*>(AS) + A_SEG(cb));

        float s[8][4];
#pragma unroll
        for (int j = 0; j < 8; j++)
#pragma unroll
            for (int c = 0; c < 4; c++) s[j][c] = 0.f;
#pragma unroll
        for (int ks = 0; ks < 4; ks++) {
            uint32_t aq[4];
            ldsm_x4(qbase + ((warp*16 + lrow)*ASTR + ks*16 + lcol8)*2,
                    aq[0], aq[1], aq[2], aq[3]);
#pragma unroll
            for (int p = 0; p < 4; p++) {
                uint32_t bf[4];
                ldsm_x4(kbase + ((p*16 + lrow)*ASTR + ks*16 + lcol8)*2,
                        bf[0], bf[1], bf[2], bf[3]);
                MMA16816(s[2*p],   aq[0], aq[1], aq[2], aq[3], bf[0], bf[2]);
                MMA16816(s[2*p+1], aq[0], aq[1], aq[2], aq[3], bf[1], bf[3]);
            }
        }

        float mt0 = -1e30f, mt1 = -1e30f;
#pragma unroll
        for (int j = 0; j < 8; j++) {
            int kg0 = k0 + 8*j + 2*qid;
            int sg0 = sseg[8*j + 2*qid];
            int sg1 = sseg[8*j + 2*qid + 1];
            s[j][0] = (kg0     <= qg0 && sg0 == qseg0) ? s[j][0] : -1e30f;
            s[j][1] = (kg0 + 1 <= qg0 && sg1 == qseg0) ? s[j][1] : -1e30f;
            s[j][2] = (kg0     <= qg1 && sg0 == qseg1) ? s[j][2] : -1e30f;
            s[j][3] = (kg0 + 1 <= qg1 && sg1 == qseg1) ? s[j][3] : -1e30f;
            mt0 = fmaxf(mt0, fmaxf(s[j][0], s[j][1]));
            mt1 = fmaxf(mt1, fmaxf(s[j][2], s[j][3]));
        }
#pragma unroll
        for (int off = 1; off < 4; off <<= 1) {
            mt0 = fmaxf(mt0, __shfl_xor_sync(0xffffffffu, mt0, off));
            mt1 = fmaxf(mt1, __shfl_xor_sync(0xffffffffu, mt1, off));
        }
        float mn0 = fmaxf(m0, mt0), mn1 = fmaxf(m1, mt1);
        float f0 = __expf(m0 - mn0), f1 = __expf(m1 - mn1);
        m0 = mn0; m1 = mn1;
        float rs0 = 0.f, rs1 = 0.f;
#pragma unroll
        for (int j = 0; j < 8; j++) {
            s[j][0] = __expf(s[j][0] - mn0);
            s[j][1] = __expf(s[j][1] - mn0);
            s[j][2] = __expf(s[j][2] - mn1);
            s[j][3] = __expf(s[j][3] - mn1);
            rs0 += s[j][0] + s[j][1];
            rs1 += s[j][2] + s[j][3];
            O[j][0] *= f0; O[j][1] *= f0;
            O[j][2] *= f1; O[j][3] *= f1;
        }
#pragma unroll
        for (int off = 1; off < 4; off <<= 1) {
            rs0 += __shfl_xor_sync(0xffffffffu, rs0, off);
            rs1 += __shfl_xor_sync(0xffffffffu, rs1, off);
        }
        l0 = l0 * f0 + rs0;
        l1 = l1 * f1 + rs1;

        uint32_t ap[4][4];
#pragma unroll
        for (int ks = 0; ks < 4; ks++) {
            ap[ks][0] = packh2(s[2*ks][0],   s[2*ks][1]);
            ap[ks][1] = packh2(s[2*ks][2],   s[2*ks][3]);
            ap[ks][2] = packh2(s[2*ks+1][0], s[2*ks+1][1]);
            ap[ks][3] = packh2(s[2*ks+1][2], s[2*ks+1][3]);
        }

#pragma unroll
        for (int ks = 0; ks < 4; ks++) {
#pragma unroll
            for (int p = 0; p < 4; p++) {
                uint32_t bv[4];
                ldsm_x4_t(vbase + ((ks*16 + lrow)*ASTR + p*16 + lcol8)*2,
                          bv[0], bv[1], bv[2], bv[3]);
                MMA16816(O[2*p],   ap[ks][0], ap[ks][1], ap[ks][2], ap[ks][3], bv[0], bv[1]);
                MMA16816(O[2*p+1], ap[ks][0], ap[ks][1], ap[ks][2], ap[ks][3], bv[2], bv[3]);
            }
        }
        __syncthreads();
    }

    float inv0 = 1.0f / l0, inv1 = 1.0f / l1;
#pragma unroll
    for (int j = 0; j < 8; j++) {
        int col = h*HD + 8*j + 2*qid;
        *reinterpret_cast<uint32_t*>(&o[(size_t)(b*LL + qg0)*DD + col]) =
            packh2(O[j][0]*inv0, O[j][1]*inv0);
        *reinterpret_cast<uint32_t*>(&o[(size_t)(b*LL + qg1)*DD + col]) =
            packh2(O[j][2]*inv1, O[j][3]*inv1);
    }
}

// ---------------------------------------------------------------------------
// add+LN, warp-per-row (R14)
// ---------------------------------------------------------------------------
__global__ __launch_bounds__(256)
void add_ln_kernel(float* __restrict__ x, const float* __restrict__ r,
                   const float* __restrict__ w, const float* __restrict__ b,
                   __half* __restrict__ hx) {
    const int wid  = threadIdx.x >> 5;
    const int lane = threadIdx.x & 31;
    const int row  = blockIdx.x * 8 + wid;

    const float4* xr = reinterpret_cast<const float4*>(x + (size_t)row*DD);
    const float4* rr = reinterpret_cast<const float4*>(r + (size_t)row*DD);
    const float4* wr = reinterpret_cast<const float4*>(w);
    const float4* br = reinterpret_cast<const float4*>(b);

    float4 v[6];
    float s = 0.f;
#pragma unroll
    for (int j = 0; j < 6; j++) {
        float4 a = xr[lane + 32*j];
        float4 c = rr[lane + 32*j];
        a.x += c.x; a.y += c.y; a.z += c.z; a.w += c.w;
        v[j] = a;
        s += a.x + a.y + a.z + a.w;
    }
#pragma unroll
    for (int off = 16; off; off >>= 1) s += __shfl_xor_sync(0xffffffffu, s, off);
    const float mean = s * (1.0f / DD);

    float vs = 0.f;
#pragma unroll
    for (int j = 0; j < 6; j++) {
        float dx = v[j].x - mean, dy = v[j].y - mean;
        float dz = v[j].z - mean, dw = v[j].w - mean;
        vs += dx*dx + dy*dy + dz*dz + dw*dw;
    }
#pragma unroll
    for (int off = 16; off; off >>= 1) vs += __shfl_xor_sync(0xffffffffu, vs, off);
    const float inv = rsqrtf(vs * (1.0f / DD) + 1e-5f);

    float4* xo = reinterpret_cast<float4*>(x + (size_t)row*DD);
    uint2*  ho = reinterpret_cast<uint2*>(hx + (size_t)row*DD);
#pragma unroll
    for (int j = 0; j < 6; j++) {
        float4 ww = wr[lane + 32*j];
        float4 bb = br[lane + 32*j];
        float4 o;
        o.x = (v[j].x - mean) * inv * ww.x + bb.x;
        o.y = (v[j].y - mean) * inv * ww.y + bb.y;
        o.z = (v[j].z - mean) * inv * ww.z + bb.z;
        o.w = (v[j].w - mean) * inv * ww.w + bb.w;
        xo[lane + 32*j] = o;
        ho[lane + 32*j] = make_uint2(packh2(o.x, o.y), packh2(o.z, o.w));
    }
}

// ---------------------------------------------------------------------------
// Host launcher
// ---------------------------------------------------------------------------
static inline void conv(const float* s, __half* d, long n) {
    int n8 = (int)(n / 8);
    int blocks = (n8 + 255) / 256;
    f2h_kernel<<<blocks, 256>>>((const float4*)s, (uint4*)d, n8);
}

extern "C" void kernel_launch(void* const* d_in, const int* in_sizes, int n_in,
                              void* d_out, int out_size) {
    const int*   ids   = (const int*)  d_in[0];
    const float* tok   = (const float*)d_in[1];
    const float* pos   = (const float*)d_in[2];
    const float* qkv_w = (const float*)d_in[3];
    const float* qkv_b = (const float*)d_in[4];
    const float* out_w = (const float*)d_in[5];
    const float* out_b = (const float*)d_in[6];
    const float* ln1_w = (const float*)d_in[7];
    const float* ln1_b = (const float*)d_in[8];
    const float* ln2_w = (const float*)d_in[9];
    const float* ln2_b = (const float*)d_in[10];
    const float* ff1_w = (const float*)d_in[11];
    const float* ff1_b = (const float*)d_in[12];
    const float* ff2_w = (const float*)d_in[13];
    const float* ff2_b = (const float*)d_in[14];
    float* out = (float*)d_out;

    float *x, *tmp;
    int *rel, *seg;
    __half *hqkv, *hx, *hatt, *hff, *htok, *hqkvw, *houtw, *hff1w, *hff2w;
    cudaGetSymbolAddress((void**)&x,    g_x);
    cudaGetSymbolAddress((void**)&tmp,  g_tmp);
    cudaGetSymbolAddress((void**)&rel,  g_rel);
    cudaGetSymbolAddress((void**)&seg,  g_seg);
    cudaGetSymbolAddress((void**)&hqkv, h_qkv);
    cudaGetSymbolAddress((void**)&hx,   h_x);
    cudaGetSymbolAddress((void**)&hatt, h_att);
    cudaGetSymbolAddress((void**)&hff,  h_ff);
    cudaGetSymbolAddress((void**)&htok, h_tok);
    cudaGetSymbolAddress((void**)&hqkvw, h_qkvw);
    cudaGetSymbolAddress((void**)&houtw, h_outw);
    cudaGetSymbolAddress((void**)&hff1w, h_ff1w);
    cudaGetSymbolAddress((void**)&hff2w, h_ff2w);

    cudaFuncSetAttribute(attn_mma_kernel,
        cudaFuncAttributeMaxDynamicSharedMemorySize, ATT_SMEM);

    // operand conversions (deterministic, every launch)
    conv(tok,   htok,  (long)VV*DD);
    conv(qkv_w, hqkvw, (long)NLAY*3*DD*DD);
    conv(out_w, houtw, (long)NLAY*DD*DD);
    conv(ff1_w, hff1w, (long)NLAY*DFFN*DD);
    conv(ff2_w, hff2w, (long)NLAY*DD*DFFN);

    meta_kernel<<<BB, 32>>>(ids, rel, seg);
    embed_kernel<<<ROWS, 192>>>(ids, rel, tok, pos, x, hx);

    const int MT = ROWS / 128;   // 16
    const int MT64 = ROWS / 64;  // 32

    for (int l = 0; l < NLAY; l++) {
        gemm_h<false,true><<<dim3(MT, 3*DD/128), 256>>>(
            hx, hqkvw + (size_t)l*3*DD*DD, qkv_b + (size_t)l*3*DD, hqkv,
            ROWS, 3*DD, DD);

        attn_mma_kernel<<<dim3(LL/128, HH, BB), 256, ATT_SMEM>>>(hqkv, seg, hatt);

        gemm_h64<<<dim3(MT64, DD/128), 256>>>(
            hatt, houtw + (size_t)l*DD*DD, out_b + (size_t)l*DD, tmp,
            ROWS, DD, DD);

        add_ln_kernel<<<ROWS/8, 256>>>(x, tmp, ln1_w + (size_t)l*DD, ln1_b + (size_t)l*DD, hx);

        gemm_h<true,true><<<dim3(MT, DFFN/128), 256>>>(
            hx, hff1w + (size_t)l*DFFN*DD, ff1_b + (size_t)l*DFFN, hff,
            ROWS, DFFN, DD);

        gemm_h64<<<dim3(MT64, DD/128), 256>>>(
            hff, hff2w + (size_t)l*DD*DFFN, ff2_b + (size_t)l*DD, tmp,
            ROWS, DD, DFFN);

        add_ln_kernel<<<ROWS/8, 256>>>(x, tmp, ln2_w + (size_t)l*DD, ln2_b + (size_t)l*DD, hx);
    }

    gemm_h<false,false><<<dim3(MT, (VV + 127)/128), 256>>>(
        hx, htok, nullptr, out, ROWS, VV, DD);
}